// round 6
// baseline (speedup 1.0000x reference)
#include <cuda_runtime.h>
#include <cstdint>

// Shapes (fixed by the problem)
#define Dd 1024
#define Tt 32
#define Bb 16
#define Ss 128
#define TG 4

// Scratch for the two projection GEMMs
__device__ float g_pi[Tt * Bb * Dd];   // [T*B, D]
__device__ float g_pc[Bb * Ss * Dd];   // [B*S, D]

// ===========================================================================
// Helpers
// ===========================================================================
__device__ __forceinline__ uint32_t smem_to_u32(const void* p) {
    uint32_t a;
    asm("{ .reg .u64 t; cvta.to.shared.u64 t, %1; cvt.u32.u64 %0, t; }" : "=r"(a) : "l"(p));
    return a;
}
__device__ __forceinline__ uint32_t pack_bf16x2(float lo, float hi) {
    uint32_t r;
    asm("cvt.rn.bf16x2.f32 %0, %1, %2;" : "=r"(r) : "f"(hi), "f"(lo));
    return r;
}
__device__ __forceinline__ void ldsm_x4(uint32_t* r, uint32_t addr) {
    asm volatile("ldmatrix.sync.aligned.m8n8.x4.shared.b16 {%0,%1,%2,%3}, [%4];"
                 : "=r"(r[0]), "=r"(r[1]), "=r"(r[2]), "=r"(r[3]) : "r"(addr));
}
__device__ __forceinline__ void mma_bf16(float* c, const uint32_t* a,
                                         uint32_t b0, uint32_t b1) {
    asm volatile(
        "mma.sync.aligned.m16n8k16.row.col.f32.bf16.bf16.f32 "
        "{%0,%1,%2,%3}, {%4,%5,%6,%7}, {%8,%9}, {%0,%1,%2,%3};"
        : "+f"(c[0]), "+f"(c[1]), "+f"(c[2]), "+f"(c[3])
        : "r"(a[0]), "r"(a[1]), "r"(a[2]), "r"(a[3]), "r"(b0), "r"(b1));
}

// split one float4 into bf16 hi/lo planes and store (uint2 each)
__device__ __forceinline__ void split_store(float4 v, char* hp, char* lp) {
    uint32_t h01 = pack_bf16x2(v.x, v.y);
    uint32_t h23 = pack_bf16x2(v.z, v.w);
    float hx = __uint_as_float(h01 << 16);
    float hy = __uint_as_float(h01 & 0xffff0000u);
    float hz = __uint_as_float(h23 << 16);
    float hw = __uint_as_float(h23 & 0xffff0000u);
    uint32_t l01 = pack_bf16x2(v.x - hx, v.y - hy);
    uint32_t l23 = pack_bf16x2(v.z - hz, v.w - hw);
    *(uint2*)hp = make_uint2(h01, h23);
    *(uint2*)lp = make_uint2(l01, l23);
}

// ===========================================================================
// bf16 3-MMA split GEMM, double-buffered:
//   C[m,n] = sum_k A[m,k]*W[n,k] + bias[n];  x = hi + lo (bf16);
//   C ~= Ah*Bh + Al*Bh + Ah*Bl  (fp32 accum)
// BM=128, BN=64, KC=16, 64 chunks. 256 threads = 8 warps (4m x 2n), warp 32x32.
// smem: 2 stages x {Ah,Al 128x16 bf16, Bh,Bl 64x16 bf16}, pitch 48 B. 36.9 KB.
// One __syncthreads per chunk; convert of chunk c+1 overlaps MMA of chunk c.
// Grid: blocks [0,64) -> pi (M=512), [64,320) -> pc (M=2048).
// ===========================================================================
#define BMt 128
#define BNt 64
#define KC  16
#define NCHUNK (Dd / KC)        // 64
#define PITCH 48                // 16 bf16 = 32B + 16B pad (multiple of 16)

__global__ void __launch_bounds__(256) gemm_kernel(
    const float* __restrict__ inputs, const float* __restrict__ context,
    const float* __restrict__ W_in,  const float* __restrict__ b_in,
    const float* __restrict__ W_ctx, const float* __restrict__ b_ctx)
{
    __shared__ __align__(16) char sAh[2][BMt * PITCH];   // 2 x 6144
    __shared__ __align__(16) char sAl[2][BMt * PITCH];
    __shared__ __align__(16) char sBh[2][BNt * PITCH];   // 2 x 3072
    __shared__ __align__(16) char sBl[2][BNt * PITCH];

    const int tid  = threadIdx.x;
    const int wid  = tid >> 5;
    const int lane = tid & 31;

    const float* A; const float* W; const float* bias; float* Cout; int tile;
    if (blockIdx.x < 64) { A = inputs;  W = W_in;  bias = b_in;  Cout = g_pi; tile = blockIdx.x; }
    else                 { A = context; W = W_ctx; bias = b_ctx; Cout = g_pc; tile = blockIdx.x - 64; }
    const int bm = (tile >> 4) * BMt;
    const int bn = (tile & 15) * BNt;

    const int warp_m = wid & 3;
    const int warp_n = wid >> 2;

    // per-thread gmem slots (float4): A: 2 (128 rows x 4 per row), B: 1 (64 x 4)
    const int aRow0 = (tid) >> 2,  aC4_0 = tid & 3;          // e = tid
    const int aRow1 = (256 + tid) >> 2, aC4_1 = tid & 3;     // e = 256+tid
    const int bRow  = tid >> 2,    bC4   = tid & 3;
    const float* aP0 = A + (size_t)(bm + aRow0) * Dd + aC4_0 * 4;
    const float* aP1 = A + (size_t)(bm + aRow1) * Dd + aC4_1 * 4;
    const float* bP  = W + (size_t)(bn + bRow) * Dd + bC4 * 4;
    const uint32_t aOff0 = (uint32_t)(aRow0 * PITCH + aC4_0 * 8);
    const uint32_t aOff1 = (uint32_t)(aRow1 * PITCH + aC4_1 * 8);
    const uint32_t bOff  = (uint32_t)(bRow * PITCH + bC4 * 8);

    // ldmatrix lane address offsets
    const int lr  = lane & 7;
    const int grp = lane >> 3;
    const uint32_t aRowOff = (uint32_t)((warp_m * 32 + (grp & 1) * 8 + lr) * PITCH
                                        + (grp >> 1) * 16);
    const uint32_t bRowOff = (uint32_t)((warp_n * 32 + (grp >> 1) * 8 + lr) * PITCH
                                        + (grp & 1) * 16);

    float acc[2][4][4];
    #pragma unroll
    for (int mi = 0; mi < 2; mi++)
        #pragma unroll
        for (int ni = 0; ni < 4; ni++)
            #pragma unroll
            for (int j = 0; j < 4; j++) acc[mi][ni][j] = 0.f;

    // ---- prologue: load + convert chunk 0 into stage 0 ----
    float4 ra0 = *(const float4*)aP0;
    float4 ra1 = *(const float4*)aP1;
    float4 rb  = *(const float4*)bP;
    split_store(ra0, sAh[0] + aOff0, sAl[0] + aOff0);
    split_store(ra1, sAh[0] + aOff1, sAl[0] + aOff1);
    split_store(rb,  sBh[0] + bOff,  sBl[0] + bOff);
    __syncthreads();

    for (int c = 0; c < NCHUNK; c++) {
        const int cur = c & 1, nxt = cur ^ 1;

        // issue gmem loads for chunk c+1 (latency hidden under MMA)
        if (c + 1 < NCHUNK) {
            const int kb = (c + 1) * KC;
            ra0 = *(const float4*)(aP0 + kb);
            ra1 = *(const float4*)(aP1 + kb);
            rb  = *(const float4*)(bP  + kb);
        }

        // compute chunk c from stage cur
        {
            uint32_t ah[2][4], al[2][4], bh[2][4], bl[2][4];
            const uint32_t baseAh = smem_to_u32(sAh[cur]) + aRowOff;
            const uint32_t baseAl = smem_to_u32(sAl[cur]) + aRowOff;
            const uint32_t baseBh = smem_to_u32(sBh[cur]) + bRowOff;
            const uint32_t baseBl = smem_to_u32(sBl[cur]) + bRowOff;
            #pragma unroll
            for (int mi = 0; mi < 2; mi++) {
                ldsm_x4(ah[mi], baseAh + mi * 16 * PITCH);
                ldsm_x4(al[mi], baseAl + mi * 16 * PITCH);
            }
            #pragma unroll
            for (int ng = 0; ng < 2; ng++) {
                ldsm_x4(bh[ng], baseBh + ng * 16 * PITCH);
                ldsm_x4(bl[ng], baseBl + ng * 16 * PITCH);
            }
            #pragma unroll
            for (int mi = 0; mi < 2; mi++)
                #pragma unroll
                for (int ni = 0; ni < 4; ni++) {
                    const int ng = ni >> 1, sel = (ni & 1) * 2;
                    mma_bf16(acc[mi][ni], ah[mi], bh[ng][sel], bh[ng][sel + 1]);
                    mma_bf16(acc[mi][ni], al[mi], bh[ng][sel], bh[ng][sel + 1]);
                    mma_bf16(acc[mi][ni], ah[mi], bl[ng][sel], bl[ng][sel + 1]);
                }
        }

        // convert + store chunk c+1 into stage nxt (waits on gmem loads)
        if (c + 1 < NCHUNK) {
            split_store(ra0, sAh[nxt] + aOff0, sAl[nxt] + aOff0);
            split_store(ra1, sAh[nxt] + aOff1, sAl[nxt] + aOff1);
            split_store(rb,  sBh[nxt] + bOff,  sBl[nxt] + bOff);
        }
        __syncthreads();
    }

    // ---- epilogue: bias add + store ----
    const int tq = lane >> 2;
    const int tr = lane & 3;
    #pragma unroll
    for (int mi = 0; mi < 2; mi++)
        #pragma unroll
        for (int ni = 0; ni < 4; ni++) {
            const int col  = bn + warp_n * 32 + ni * 8 + tr * 2;
            const int row0 = bm + warp_m * 32 + mi * 16 + tq;
            const float2 bv = *(const float2*)(bias + col);
            float2 o0, o1;
            o0.x = acc[mi][ni][0] + bv.x;  o0.y = acc[mi][ni][1] + bv.y;
            o1.x = acc[mi][ni][2] + bv.x;  o1.y = acc[mi][ni][3] + bv.y;
            *(float2*)(Cout + (size_t)row0 * Dd + col)       = o0;
            *(float2*)(Cout + (size_t)(row0 + 8) * Dd + col) = o1;
        }
}

// ===========================================================================
// Fused scores -> softmax -> weighted context sum.
// 512 threads/CTA (16 warps) to double issue bandwidth; __launch_bounds__
// caps regs at 128 (score-loop unroll reduced 8 -> 2).
// Final phase split across two 256-thread groups (tt pairs).
// ===========================================================================
#define SWISH_ACC(accv, pic, pcc, wc)                                    \
    {                                                                    \
        float c_ = (pic) + (pcc);                                        \
        float h_ = 0.5f * c_;                                            \
        float th_;                                                       \
        asm("tanh.approx.f32 %0, %1;" : "=f"(th_) : "f"(h_));            \
        (accv) = fmaf(fmaf(th_, h_, h_), (wc), (accv));                  \
    }

__global__ void __launch_bounds__(512) attn_kernel(
    const float* __restrict__ context,
    const float* __restrict__ w_one,
    float* __restrict__ out)
{
    const int b  = blockIdx.x & (Bb - 1);
    const int tg = blockIdx.x >> 4;

    __shared__ __align__(16) float4 s_pi[TG][Dd / 4];
    __shared__ __align__(16) float4 s_w[Dd / 4];
    __shared__ float s_sc[TG][Ss];

    const int tid  = threadIdx.x;
    const int lane = tid & 31;
    const int warp = tid >> 5;          // 0..15

    if (tid < Dd / 4) {
        s_w[tid] = ((const float4*)w_one)[tid];
        #pragma unroll
        for (int tt = 0; tt < TG; tt++) {
            const int tb = (tg * TG + tt) * Bb + b;
            s_pi[tt][tid] = ((const float4*)(g_pi + (size_t)tb * Dd))[tid];
        }
    }
    __syncthreads();

    // ---- scores[tt][s] = sum_d swish(pi[tt,d] + pc[s,d]) * w[d] ----
    const float* pcb = g_pc + (size_t)b * Ss * Dd;
    for (int s = warp; s < Ss; s += 16) {
        const float4* row = (const float4*)(pcb + (size_t)s * Dd);
        float acc[TG] = {0.f, 0.f, 0.f, 0.f};
        #pragma unroll 2
        for (int i = 0; i < 8; i++) {
            const int idx = i * 32 + lane;
            const float4 pcv = row[idx];
            const float4 wv  = s_w[idx];
            #pragma unroll
            for (int tt = 0; tt < TG; tt++) {
                const float4 piv = s_pi[tt][idx];
                SWISH_ACC(acc[tt], piv.x, pcv.x, wv.x);
                SWISH_ACC(acc[tt], piv.y, pcv.y, wv.y);
                SWISH_ACC(acc[tt], piv.z, pcv.z, wv.z);
                SWISH_ACC(acc[tt], piv.w, pcv.w, wv.w);
            }
        }
        #pragma unroll
        for (int tt = 0; tt < TG; tt++) {
            float a = acc[tt];
            #pragma unroll
            for (int o = 16; o > 0; o >>= 1)
                a += __shfl_xor_sync(0xffffffffu, a, o);
            if (lane == 0) s_sc[tt][s] = a;
        }
    }
    __syncthreads();

    // ---- softmax: warp tt handles row tt ----
    if (warp < TG) {
        const int tt = warp;
        float v0 = s_sc[tt][lane];
        float v1 = s_sc[tt][lane + 32];
        float v2 = s_sc[tt][lane + 64];
        float v3 = s_sc[tt][lane + 96];
        float m = fmaxf(fmaxf(v0, v1), fmaxf(v2, v3));
        #pragma unroll
        for (int o = 16; o > 0; o >>= 1)
            m = fmaxf(m, __shfl_xor_sync(0xffffffffu, m, o));
        float p0 = __expf(v0 - m), p1 = __expf(v1 - m);
        float p2 = __expf(v2 - m), p3 = __expf(v3 - m);
        float sum = p0 + p1 + p2 + p3;
        #pragma unroll
        for (int o = 16; o > 0; o >>= 1)
            sum += __shfl_xor_sync(0xffffffffu, sum, o);
        const float inv = __fdividef(1.f, sum);
        const int tb = (tg * TG + tt) * Bb + b;
        float* attn_out = out + (size_t)Tt * Bb * Dd + (size_t)tb * Ss;
        p0 *= inv; p1 *= inv; p2 *= inv; p3 *= inv;
        s_sc[tt][lane]      = p0;  attn_out[lane]      = p0;
        s_sc[tt][lane + 32] = p1;  attn_out[lane + 32] = p1;
        s_sc[tt][lane + 64] = p2;  attn_out[lane + 64] = p2;
        s_sc[tt][lane + 96] = p3;  attn_out[lane + 96] = p3;
    }
    __syncthreads();

    // ---- attn_context: group g = tid>>8 handles tt in {2g, 2g+1} ----
    const int col = tid & 255;
    const int g   = tid >> 8;
    const float4* ctx4 = (const float4*)(context + (size_t)b * Ss * Dd);
    float4 acc0 = make_float4(0.f, 0.f, 0.f, 0.f);
    float4 acc1 = make_float4(0.f, 0.f, 0.f, 0.f);

    #pragma unroll 4
    for (int s = 0; s < Ss; s++) {
        const float4 c = ctx4[(size_t)s * (Dd / 4) + col];
        const float a0 = s_sc[2 * g + 0][s];
        const float a1 = s_sc[2 * g + 1][s];
        acc0.x = fmaf(a0, c.x, acc0.x);  acc0.y = fmaf(a0, c.y, acc0.y);
        acc0.z = fmaf(a0, c.z, acc0.z);  acc0.w = fmaf(a0, c.w, acc0.w);
        acc1.x = fmaf(a1, c.x, acc1.x);  acc1.y = fmaf(a1, c.y, acc1.y);
        acc1.z = fmaf(a1, c.z, acc1.z);  acc1.w = fmaf(a1, c.w, acc1.w);
    }
    {
        const int tb0 = (tg * TG + 2 * g + 0) * Bb + b;
        const int tb1 = (tg * TG + 2 * g + 1) * Bb + b;
        ((float4*)(out + (size_t)tb0 * Dd))[col] = acc0;
        ((float4*)(out + (size_t)tb1 * Dd))[col] = acc1;
    }
}

// ===========================================================================
extern "C" void kernel_launch(void* const* d_in, const int* in_sizes, int n_in,
                              void* d_out, int out_size) {
    const float* inputs  = (const float*)d_in[0];
    const float* context = (const float*)d_in[1];
    const float* W_in    = (const float*)d_in[2];
    const float* b_in    = (const float*)d_in[3];
    const float* W_ctx   = (const float*)d_in[4];
    const float* b_ctx   = (const float*)d_in[5];
    const float* w_one   = (const float*)d_in[6];
    // d_in[7] = b_one: softmax is shift-invariant -> no effect on outputs.
    float* out = (float*)d_out;

    gemm_kernel<<<320, 256>>>(inputs, context, W_in, b_in, W_ctx, b_ctx);
    attn_kernel<<<Bb * (Tt / TG), 512>>>(context, w_one, out);
}

// round 7
// speedup vs baseline: 1.0503x; 1.0503x over previous
#include <cuda_runtime.h>
#include <cstdint>

// Shapes (fixed by the problem)
#define Dd 1024
#define Tt 32
#define Bb 16
#define Ss 128
#define TG 2            // t-values per attn CTA (grid = 16 * 16 = 256)

// Scratch for the two projection GEMMs
__device__ float g_pi[Tt * Bb * Dd];   // [T*B, D]
__device__ float g_pc[Bb * Ss * Dd];   // [B*S, D]

// ===========================================================================
// Helpers
// ===========================================================================
__device__ __forceinline__ uint32_t smem_to_u32(const void* p) {
    uint32_t a;
    asm("{ .reg .u64 t; cvta.to.shared.u64 t, %1; cvt.u32.u64 %0, t; }" : "=r"(a) : "l"(p));
    return a;
}
__device__ __forceinline__ uint32_t pack_bf16x2(float lo, float hi) {
    uint32_t r;
    asm("cvt.rn.bf16x2.f32 %0, %1, %2;" : "=r"(r) : "f"(hi), "f"(lo));
    return r;
}
__device__ __forceinline__ void ldsm_x4(uint32_t* r, uint32_t addr) {
    asm volatile("ldmatrix.sync.aligned.m8n8.x4.shared.b16 {%0,%1,%2,%3}, [%4];"
                 : "=r"(r[0]), "=r"(r[1]), "=r"(r[2]), "=r"(r[3]) : "r"(addr));
}
__device__ __forceinline__ void mma_bf16(float* c, const uint32_t* a,
                                         uint32_t b0, uint32_t b1) {
    asm volatile(
        "mma.sync.aligned.m16n8k16.row.col.f32.bf16.bf16.f32 "
        "{%0,%1,%2,%3}, {%4,%5,%6,%7}, {%8,%9}, {%0,%1,%2,%3};"
        : "+f"(c[0]), "+f"(c[1]), "+f"(c[2]), "+f"(c[3])
        : "r"(a[0]), "r"(a[1]), "r"(a[2]), "r"(a[3]), "r"(b0), "r"(b1));
}
__device__ __forceinline__ void split_store(float4 v, char* hp, char* lp) {
    uint32_t h01 = pack_bf16x2(v.x, v.y);
    uint32_t h23 = pack_bf16x2(v.z, v.w);
    float hx = __uint_as_float(h01 << 16);
    float hy = __uint_as_float(h01 & 0xffff0000u);
    float hz = __uint_as_float(h23 << 16);
    float hw = __uint_as_float(h23 & 0xffff0000u);
    uint32_t l01 = pack_bf16x2(v.x - hx, v.y - hy);
    uint32_t l23 = pack_bf16x2(v.z - hz, v.w - hw);
    *(uint2*)hp = make_uint2(h01, h23);
    *(uint2*)lp = make_uint2(l01, l23);
}

// ===========================================================================
// bf16 3-MMA split GEMM, double-buffered (UNCHANGED from R6, measured ~59us).
// ===========================================================================
#define BMt 128
#define BNt 64
#define KC  16
#define NCHUNK (Dd / KC)        // 64
#define PITCH 48

__global__ void __launch_bounds__(256) gemm_kernel(
    const float* __restrict__ inputs, const float* __restrict__ context,
    const float* __restrict__ W_in,  const float* __restrict__ b_in,
    const float* __restrict__ W_ctx, const float* __restrict__ b_ctx)
{
    __shared__ __align__(16) char sAh[2][BMt * PITCH];
    __shared__ __align__(16) char sAl[2][BMt * PITCH];
    __shared__ __align__(16) char sBh[2][BNt * PITCH];
    __shared__ __align__(16) char sBl[2][BNt * PITCH];

    const int tid  = threadIdx.x;
    const int wid  = tid >> 5;
    const int lane = tid & 31;

    const float* A; const float* W; const float* bias; float* Cout; int tile;
    if (blockIdx.x < 64) { A = inputs;  W = W_in;  bias = b_in;  Cout = g_pi; tile = blockIdx.x; }
    else                 { A = context; W = W_ctx; bias = b_ctx; Cout = g_pc; tile = blockIdx.x - 64; }
    const int bm = (tile >> 4) * BMt;
    const int bn = (tile & 15) * BNt;

    const int warp_m = wid & 3;
    const int warp_n = wid >> 2;

    const int aRow0 = tid >> 2,         aC4_0 = tid & 3;
    const int aRow1 = (256 + tid) >> 2, aC4_1 = tid & 3;
    const int bRow  = tid >> 2,         bC4   = tid & 3;
    const float* aP0 = A + (size_t)(bm + aRow0) * Dd + aC4_0 * 4;
    const float* aP1 = A + (size_t)(bm + aRow1) * Dd + aC4_1 * 4;
    const float* bP  = W + (size_t)(bn + bRow) * Dd + bC4 * 4;
    const uint32_t aOff0 = (uint32_t)(aRow0 * PITCH + aC4_0 * 8);
    const uint32_t aOff1 = (uint32_t)(aRow1 * PITCH + aC4_1 * 8);
    const uint32_t bOff  = (uint32_t)(bRow * PITCH + bC4 * 8);

    const int lr  = lane & 7;
    const int grp = lane >> 3;
    const uint32_t aRowOff = (uint32_t)((warp_m * 32 + (grp & 1) * 8 + lr) * PITCH
                                        + (grp >> 1) * 16);
    const uint32_t bRowOff = (uint32_t)((warp_n * 32 + (grp >> 1) * 8 + lr) * PITCH
                                        + (grp & 1) * 16);

    float acc[2][4][4];
    #pragma unroll
    for (int mi = 0; mi < 2; mi++)
        #pragma unroll
        for (int ni = 0; ni < 4; ni++)
            #pragma unroll
            for (int j = 0; j < 4; j++) acc[mi][ni][j] = 0.f;

    float4 ra0 = *(const float4*)aP0;
    float4 ra1 = *(const float4*)aP1;
    float4 rb  = *(const float4*)bP;
    split_store(ra0, sAh[0] + aOff0, sAl[0] + aOff0);
    split_store(ra1, sAh[0] + aOff1, sAl[0] + aOff1);
    split_store(rb,  sBh[0] + bOff,  sBl[0] + bOff);
    __syncthreads();

    for (int c = 0; c < NCHUNK; c++) {
        const int cur = c & 1, nxt = cur ^ 1;

        if (c + 1 < NCHUNK) {
            const int kb = (c + 1) * KC;
            ra0 = *(const float4*)(aP0 + kb);
            ra1 = *(const float4*)(aP1 + kb);
            rb  = *(const float4*)(bP  + kb);
        }

        {
            uint32_t ah[2][4], al[2][4], bh[2][4], bl[2][4];
            const uint32_t baseAh = smem_to_u32(sAh[cur]) + aRowOff;
            const uint32_t baseAl = smem_to_u32(sAl[cur]) + aRowOff;
            const uint32_t baseBh = smem_to_u32(sBh[cur]) + bRowOff;
            const uint32_t baseBl = smem_to_u32(sBl[cur]) + bRowOff;
            #pragma unroll
            for (int mi = 0; mi < 2; mi++) {
                ldsm_x4(ah[mi], baseAh + mi * 16 * PITCH);
                ldsm_x4(al[mi], baseAl + mi * 16 * PITCH);
            }
            #pragma unroll
            for (int ng = 0; ng < 2; ng++) {
                ldsm_x4(bh[ng], baseBh + ng * 16 * PITCH);
                ldsm_x4(bl[ng], baseBl + ng * 16 * PITCH);
            }
            #pragma unroll
            for (int mi = 0; mi < 2; mi++)
                #pragma unroll
                for (int ni = 0; ni < 4; ni++) {
                    const int ng = ni >> 1, sel = (ni & 1) * 2;
                    mma_bf16(acc[mi][ni], ah[mi], bh[ng][sel], bh[ng][sel + 1]);
                    mma_bf16(acc[mi][ni], al[mi], bh[ng][sel], bh[ng][sel + 1]);
                    mma_bf16(acc[mi][ni], ah[mi], bl[ng][sel], bl[ng][sel + 1]);
                }
        }

        if (c + 1 < NCHUNK) {
            split_store(ra0, sAh[nxt] + aOff0, sAl[nxt] + aOff0);
            split_store(ra1, sAh[nxt] + aOff1, sAl[nxt] + aOff1);
            split_store(rb,  sBh[nxt] + bOff,  sBl[nxt] + bOff);
        }
        __syncthreads();
    }

    const int tq = lane >> 2;
    const int tr = lane & 3;
    #pragma unroll
    for (int mi = 0; mi < 2; mi++)
        #pragma unroll
        for (int ni = 0; ni < 4; ni++) {
            const int col  = bn + warp_n * 32 + ni * 8 + tr * 2;
            const int row0 = bm + warp_m * 32 + mi * 16 + tq;
            const float2 bv = *(const float2*)(bias + col);
            float2 o0, o1;
            o0.x = acc[mi][ni][0] + bv.x;  o0.y = acc[mi][ni][1] + bv.y;
            o1.x = acc[mi][ni][2] + bv.x;  o1.y = acc[mi][ni][3] + bv.y;
            *(float2*)(Cout + (size_t)row0 * Dd + col)       = o0;
            *(float2*)(Cout + (size_t)(row0 + 8) * Dd + col) = o1;
        }
}

// ===========================================================================
// Fused scores -> softmax -> weighted context sum.
// TG=2, 256 threads, grid 256 CTAs, __launch_bounds__(256, 2) -> 2 CTAs/SM
// (16 warps/SM) while keeping unroll-4 ILP in the score loop.
// ===========================================================================
#define SWISH_ACC(accv, pic, pcc, wc)                                    \
    {                                                                    \
        float c_ = (pic) + (pcc);                                        \
        float h_ = 0.5f * c_;                                            \
        float th_;                                                       \
        asm("tanh.approx.f32 %0, %1;" : "=f"(th_) : "f"(h_));            \
        (accv) = fmaf(fmaf(th_, h_, h_), (wc), (accv));                  \
    }

__global__ void __launch_bounds__(256, 2) attn_kernel(
    const float* __restrict__ context,
    const float* __restrict__ w_one,
    float* __restrict__ out)
{
    const int b  = blockIdx.x & (Bb - 1);
    const int tg = blockIdx.x >> 4;          // 0..15 ; t = tg*2 + tt

    __shared__ __align__(16) float4 s_pi[TG][Dd / 4];
    __shared__ __align__(16) float4 s_w[Dd / 4];
    __shared__ float s_sc[TG][Ss];

    const int tid  = threadIdx.x;
    const int lane = tid & 31;
    const int warp = tid >> 5;               // 0..7

    s_w[tid] = ((const float4*)w_one)[tid];
    #pragma unroll
    for (int tt = 0; tt < TG; tt++) {
        const int tb = (tg * TG + tt) * Bb + b;
        s_pi[tt][tid] = ((const float4*)(g_pi + (size_t)tb * Dd))[tid];
    }
    __syncthreads();

    // ---- scores[tt][s] = sum_d swish(pi[tt,d] + pc[s,d]) * w[d] ----
    const float* pcb = g_pc + (size_t)b * Ss * Dd;
    for (int s = warp; s < Ss; s += 8) {
        const float4* row = (const float4*)(pcb + (size_t)s * Dd);
        float acc0 = 0.f, acc1 = 0.f;
        #pragma unroll 4
        for (int i = 0; i < 8; i++) {
            const int idx = i * 32 + lane;
            const float4 pcv = row[idx];
            const float4 wv  = s_w[idx];
            const float4 p0  = s_pi[0][idx];
            const float4 p1  = s_pi[1][idx];
            SWISH_ACC(acc0, p0.x, pcv.x, wv.x);
            SWISH_ACC(acc0, p0.y, pcv.y, wv.y);
            SWISH_ACC(acc0, p0.z, pcv.z, wv.z);
            SWISH_ACC(acc0, p0.w, pcv.w, wv.w);
            SWISH_ACC(acc1, p1.x, pcv.x, wv.x);
            SWISH_ACC(acc1, p1.y, pcv.y, wv.y);
            SWISH_ACC(acc1, p1.z, pcv.z, wv.z);
            SWISH_ACC(acc1, p1.w, pcv.w, wv.w);
        }
        #pragma unroll
        for (int o = 16; o > 0; o >>= 1) {
            acc0 += __shfl_xor_sync(0xffffffffu, acc0, o);
            acc1 += __shfl_xor_sync(0xffffffffu, acc1, o);
        }
        if (lane == 0) { s_sc[0][s] = acc0; s_sc[1][s] = acc1; }
    }
    __syncthreads();

    // ---- softmax: warp tt (<2) handles row tt ----
    if (warp < TG) {
        const int tt = warp;
        float v0 = s_sc[tt][lane];
        float v1 = s_sc[tt][lane + 32];
        float v2 = s_sc[tt][lane + 64];
        float v3 = s_sc[tt][lane + 96];
        float m = fmaxf(fmaxf(v0, v1), fmaxf(v2, v3));
        #pragma unroll
        for (int o = 16; o > 0; o >>= 1)
            m = fmaxf(m, __shfl_xor_sync(0xffffffffu, m, o));
        float p0 = __expf(v0 - m), p1 = __expf(v1 - m);
        float p2 = __expf(v2 - m), p3 = __expf(v3 - m);
        float sum = p0 + p1 + p2 + p3;
        #pragma unroll
        for (int o = 16; o > 0; o >>= 1)
            sum += __shfl_xor_sync(0xffffffffu, sum, o);
        const float inv = __fdividef(1.f, sum);
        const int tb = (tg * TG + tt) * Bb + b;
        float* attn_out = out + (size_t)Tt * Bb * Dd + (size_t)tb * Ss;
        p0 *= inv; p1 *= inv; p2 *= inv; p3 *= inv;
        s_sc[tt][lane]      = p0;  attn_out[lane]      = p0;
        s_sc[tt][lane + 32] = p1;  attn_out[lane + 32] = p1;
        s_sc[tt][lane + 64] = p2;  attn_out[lane + 64] = p2;
        s_sc[tt][lane + 96] = p3;  attn_out[lane + 96] = p3;
    }
    __syncthreads();

    // ---- attn_context[t,b,:] = sum_s attn[t,s] * context[b,s,:] ----
    const float4* ctx4 = (const float4*)(context + (size_t)b * Ss * Dd);
    float4 acc0 = make_float4(0.f, 0.f, 0.f, 0.f);
    float4 acc1 = make_float4(0.f, 0.f, 0.f, 0.f);

    #pragma unroll 4
    for (int s = 0; s < Ss; s++) {
        const float4 c = ctx4[(size_t)s * (Dd / 4) + tid];
        const float a0 = s_sc[0][s];
        const float a1 = s_sc[1][s];
        acc0.x = fmaf(a0, c.x, acc0.x);  acc0.y = fmaf(a0, c.y, acc0.y);
        acc0.z = fmaf(a0, c.z, acc0.z);  acc0.w = fmaf(a0, c.w, acc0.w);
        acc1.x = fmaf(a1, c.x, acc1.x);  acc1.y = fmaf(a1, c.y, acc1.y);
        acc1.z = fmaf(a1, c.z, acc1.z);  acc1.w = fmaf(a1, c.w, acc1.w);
    }
    {
        const int tb0 = (tg * TG + 0) * Bb + b;
        const int tb1 = (tg * TG + 1) * Bb + b;
        ((float4*)(out + (size_t)tb0 * Dd))[tid] = acc0;
        ((float4*)(out + (size_t)tb1 * Dd))[tid] = acc1;
    }
}

// ===========================================================================
extern "C" void kernel_launch(void* const* d_in, const int* in_sizes, int n_in,
                              void* d_out, int out_size) {
    const float* inputs  = (const float*)d_in[0];
    const float* context = (const float*)d_in[1];
    const float* W_in    = (const float*)d_in[2];
    const float* b_in    = (const float*)d_in[3];
    const float* W_ctx   = (const float*)d_in[4];
    const float* b_ctx   = (const float*)d_in[5];
    const float* w_one   = (const float*)d_in[6];
    // d_in[7] = b_one: softmax is shift-invariant -> no effect on outputs.
    float* out = (float*)d_out;

    gemm_kernel<<<320, 256>>>(inputs, context, W_in, b_in, W_ctx, b_ctx);
    attn_kernel<<<Bb * (Tt / TG), 256>>>(context, w_one, out);
}

// round 8
// speedup vs baseline: 1.1196x; 1.0660x over previous
#include <cuda_runtime.h>
#include <cstdint>

// Shapes (fixed by the problem)
#define Dd 1024
#define Tt 32
#define Bb 16
#define Ss 128
#define TG 2            // t-values per attn CTA (grid = 256)

// Scratch for the two projection GEMMs
__device__ float g_pi[Tt * Bb * Dd];   // [T*B, D]
__device__ float g_pc[Bb * Ss * Dd];   // [B*S, D]

// ===========================================================================
// Helpers
// ===========================================================================
__device__ __forceinline__ uint32_t smem_to_u32(const void* p) {
    uint32_t a;
    asm("{ .reg .u64 t; cvta.to.shared.u64 t, %1; cvt.u32.u64 %0, t; }" : "=r"(a) : "l"(p));
    return a;
}
__device__ __forceinline__ uint32_t pack_bf16x2(float lo, float hi) {
    uint32_t r;
    asm("cvt.rn.bf16x2.f32 %0, %1, %2;" : "=r"(r) : "f"(hi), "f"(lo));
    return r;
}
__device__ __forceinline__ void ldsm_x4(uint32_t* r, uint32_t addr) {
    asm volatile("ldmatrix.sync.aligned.m8n8.x4.shared.b16 {%0,%1,%2,%3}, [%4];"
                 : "=r"(r[0]), "=r"(r[1]), "=r"(r[2]), "=r"(r[3]) : "r"(addr));
}
__device__ __forceinline__ void mma_bf16(float* c, const uint32_t* a,
                                         uint32_t b0, uint32_t b1) {
    asm volatile(
        "mma.sync.aligned.m16n8k16.row.col.f32.bf16.bf16.f32 "
        "{%0,%1,%2,%3}, {%4,%5,%6,%7}, {%8,%9}, {%0,%1,%2,%3};"
        : "+f"(c[0]), "+f"(c[1]), "+f"(c[2]), "+f"(c[3])
        : "r"(a[0]), "r"(a[1]), "r"(a[2]), "r"(a[3]), "r"(b0), "r"(b1));
}
__device__ __forceinline__ void split_store(float4 v, char* hp, char* lp) {
    uint32_t h01 = pack_bf16x2(v.x, v.y);
    uint32_t h23 = pack_bf16x2(v.z, v.w);
    float hx = __uint_as_float(h01 << 16);
    float hy = __uint_as_float(h01 & 0xffff0000u);
    float hz = __uint_as_float(h23 << 16);
    float hw = __uint_as_float(h23 & 0xffff0000u);
    uint32_t l01 = pack_bf16x2(v.x - hx, v.y - hy);
    uint32_t l23 = pack_bf16x2(v.z - hz, v.w - hw);
    *(uint2*)hp = make_uint2(h01, h23);
    *(uint2*)lp = make_uint2(l01, l23);
}
__device__ __forceinline__ uint32_t swz(uint32_t off) {      // SW128 swizzle
    return off ^ ((off >> 3) & 0x70);
}

// ===========================================================================
// bf16 3-MMA split GEMM, double-buffered, KC=32, SW128-swizzled 128B rows
// with hi plane in bytes [0,64) and lo plane in [64,128) of each row.
// BM=128, BN=64. 256 threads = 8 warps (4m x 2n), warp tile 32x32.
// smem: 2 stages x (A 16KB + B 8KB) = 49152 B (exactly the 48KB static cap).
// Per chunk: 2 k16 steps -> 16 ldsm + 48 MMA; ONE __syncthreads.
// Grid: blocks [0,64) -> pi (M=512), [64,320) -> pc (M=2048).
// ===========================================================================
#define BMt 128
#define BNt 64
#define KC  32
#define NCHUNK (Dd / KC)        // 32

__global__ void __launch_bounds__(256, 2) gemm_kernel(
    const float* __restrict__ inputs, const float* __restrict__ context,
    const float* __restrict__ W_in,  const float* __restrict__ b_in,
    const float* __restrict__ W_ctx, const float* __restrict__ b_ctx)
{
    __shared__ __align__(1024) char sbuf[2][24576];   // [stage]: A 16384 | B 8192

    const int tid  = threadIdx.x;
    const int wid  = tid >> 5;
    const int lane = tid & 31;

    const float* A; const float* W; const float* bias; float* Cout; int tile;
    if (blockIdx.x < 64) { A = inputs;  W = W_in;  bias = b_in;  Cout = g_pi; tile = blockIdx.x; }
    else                 { A = context; W = W_ctx; bias = b_ctx; Cout = g_pc; tile = blockIdx.x - 64; }
    const int bm = (tile >> 4) * BMt;
    const int bn = (tile & 15) * BNt;

    const int warp_m = wid & 3;
    const int warp_n = wid >> 2;

    // gmem slots: A: 4 float4 (128 rows x 8 f4/row), B: 2 float4 (64 x 8)
    // e = i*256 + tid -> row = e>>3, c4 = e&7
    const float* aP[4]; uint32_t aHi[4];
    #pragma unroll
    for (int i = 0; i < 4; i++) {
        const int e = i * 256 + tid;
        aP[i]  = A + (size_t)(bm + (e >> 3)) * Dd + (e & 7) * 4;
        aHi[i] = (uint32_t)((e >> 3) * 128 + (e & 7) * 8);
    }
    const float* bP[2]; uint32_t bHi[2];
    #pragma unroll
    for (int i = 0; i < 2; i++) {
        const int e = i * 256 + tid;
        bP[i]  = W + (size_t)(bn + (e >> 3)) * Dd + (e & 7) * 4;
        bHi[i] = (uint32_t)((e >> 3) * 128 + (e & 7) * 8);
    }

    // ldmatrix lane row/col pieces
    const int lr  = lane & 7;
    const int grp = lane >> 3;
    const uint32_t rowA0 = (uint32_t)(warp_m * 32 + (grp & 1) * 8 + lr) * 128;
    const uint32_t colA  = (uint32_t)((grp >> 1) * 16);
    const uint32_t rowB0 = (uint32_t)(warp_n * 32 + (grp >> 1) * 8 + lr) * 128;
    const uint32_t colB  = (uint32_t)((grp & 1) * 16);

    float acc[2][4][4];
    #pragma unroll
    for (int mi = 0; mi < 2; mi++)
        #pragma unroll
        for (int ni = 0; ni < 4; ni++)
            #pragma unroll
            for (int j = 0; j < 4; j++) acc[mi][ni][j] = 0.f;

    // prologue: chunk 0 -> stage 0
    float4 ra[4], rb[2];
    #pragma unroll
    for (int i = 0; i < 4; i++) ra[i] = *(const float4*)aP[i];
    #pragma unroll
    for (int i = 0; i < 2; i++) rb[i] = *(const float4*)bP[i];
    #pragma unroll
    for (int i = 0; i < 4; i++)
        split_store(ra[i], sbuf[0] + swz(aHi[i]), sbuf[0] + swz(aHi[i] + 64));
    #pragma unroll
    for (int i = 0; i < 2; i++)
        split_store(rb[i], sbuf[0] + 16384 + swz(bHi[i]), sbuf[0] + 16384 + swz(bHi[i] + 64));
    __syncthreads();

    for (int c = 0; c < NCHUNK; c++) {
        const int cur = c & 1, nxt = cur ^ 1;

        if (c + 1 < NCHUNK) {
            const int kb = (c + 1) * KC;
            #pragma unroll
            for (int i = 0; i < 4; i++) ra[i] = *(const float4*)(aP[i] + kb);
            #pragma unroll
            for (int i = 0; i < 2; i++) rb[i] = *(const float4*)(bP[i] + kb);
        }

        const uint32_t baseA = smem_to_u32(sbuf[cur]);
        const uint32_t baseB = baseA + 16384;
        #pragma unroll
        for (int ks = 0; ks < 2; ks++) {
            const uint32_t kOff = (uint32_t)(ks * 32);
            uint32_t ah[2][4], al[2][4], bh[2][4], bl[2][4];
            #pragma unroll
            for (int mi = 0; mi < 2; mi++) {
                const uint32_t r = rowA0 + (uint32_t)(mi * 16 * 128);
                ldsm_x4(ah[mi], baseA + swz(r + kOff + colA));
                ldsm_x4(al[mi], baseA + swz(r + 64 + kOff + colA));
            }
            #pragma unroll
            for (int ng = 0; ng < 2; ng++) {
                const uint32_t r = rowB0 + (uint32_t)(ng * 16 * 128);
                ldsm_x4(bh[ng], baseB + swz(r + kOff + colB));
                ldsm_x4(bl[ng], baseB + swz(r + 64 + kOff + colB));
            }
            #pragma unroll
            for (int mi = 0; mi < 2; mi++)
                #pragma unroll
                for (int ni = 0; ni < 4; ni++) {
                    const int ng = ni >> 1, sel = (ni & 1) * 2;
                    mma_bf16(acc[mi][ni], ah[mi], bh[ng][sel], bh[ng][sel + 1]);
                    mma_bf16(acc[mi][ni], al[mi], bh[ng][sel], bh[ng][sel + 1]);
                    mma_bf16(acc[mi][ni], ah[mi], bl[ng][sel], bl[ng][sel + 1]);
                }
        }

        if (c + 1 < NCHUNK) {
            #pragma unroll
            for (int i = 0; i < 4; i++)
                split_store(ra[i], sbuf[nxt] + swz(aHi[i]), sbuf[nxt] + swz(aHi[i] + 64));
            #pragma unroll
            for (int i = 0; i < 2; i++)
                split_store(rb[i], sbuf[nxt] + 16384 + swz(bHi[i]),
                            sbuf[nxt] + 16384 + swz(bHi[i] + 64));
        }
        __syncthreads();
    }

    // epilogue: bias add + store
    const int tq = lane >> 2;
    const int tr = lane & 3;
    #pragma unroll
    for (int mi = 0; mi < 2; mi++)
        #pragma unroll
        for (int ni = 0; ni < 4; ni++) {
            const int col  = bn + warp_n * 32 + ni * 8 + tr * 2;
            const int row0 = bm + warp_m * 32 + mi * 16 + tq;
            const float2 bv = *(const float2*)(bias + col);
            float2 o0, o1;
            o0.x = acc[mi][ni][0] + bv.x;  o0.y = acc[mi][ni][1] + bv.y;
            o1.x = acc[mi][ni][2] + bv.x;  o1.y = acc[mi][ni][3] + bv.y;
            *(float2*)(Cout + (size_t)row0 * Dd + col)       = o0;
            *(float2*)(Cout + (size_t)(row0 + 8) * Dd + col) = o1;
        }
}

// ===========================================================================
// Fused scores -> softmax -> weighted context sum.
// Warp w owns d-slice [128w, 128w+128): pi (both t's) and w_one live in
// REGISTERS for the whole score loop; only pc is loaded (1 float4/lane/s).
// Partial scores -> s_part[tt][s][warp] -> 8-way smem reduce -> softmax.
// TG=2, 256 threads, grid 256.
// ===========================================================================
#define SWISH_ACC(accv, pic, pcc, wc)                                    \
    {                                                                    \
        float c_ = (pic) + (pcc);                                        \
        float h_ = 0.5f * c_;                                            \
        float th_;                                                       \
        asm("tanh.approx.f32 %0, %1;" : "=f"(th_) : "f"(h_));            \
        (accv) = fmaf(fmaf(th_, h_, h_), (wc), (accv));                  \
    }

__global__ void __launch_bounds__(256, 2) attn_kernel(
    const float* __restrict__ context,
    const float* __restrict__ w_one,
    float* __restrict__ out)
{
    const int b  = blockIdx.x & (Bb - 1);
    const int tg = blockIdx.x >> 4;          // 0..15 ; t = tg*2 + tt

    __shared__ __align__(16) float s_part[TG][Ss][8];
    __shared__ float s_sc[TG][Ss];

    const int tid  = threadIdx.x;
    const int lane = tid & 31;
    const int warp = tid >> 5;               // 0..7 -> d-slice

    const int tb0 = (tg * TG + 0) * Bb + b;
    const int tb1 = tb0 + Bb;
    const int di  = warp * 32 + lane;        // float4 index into D/4 = 256

    const float4 pi0 = ((const float4*)g_pi)[(size_t)tb0 * (Dd / 4) + di];
    const float4 pi1 = ((const float4*)g_pi)[(size_t)tb1 * (Dd / 4) + di];
    const float4 wv  = ((const float4*)w_one)[di];
    const float4* pc4 = (const float4*)g_pc + (size_t)b * Ss * (Dd / 4);

    // ---- partial scores over this warp's 128-d slice, all 128 s ----
    for (int s0 = 0; s0 < Ss; s0 += 4) {
        float4 pc[4];
        #pragma unroll
        for (int u = 0; u < 4; u++)
            pc[u] = pc4[(size_t)(s0 + u) * (Dd / 4) + di];
        #pragma unroll
        for (int u = 0; u < 4; u++) {
            float a0 = 0.f, a1 = 0.f;
            SWISH_ACC(a0, pi0.x, pc[u].x, wv.x);
            SWISH_ACC(a0, pi0.y, pc[u].y, wv.y);
            SWISH_ACC(a0, pi0.z, pc[u].z, wv.z);
            SWISH_ACC(a0, pi0.w, pc[u].w, wv.w);
            SWISH_ACC(a1, pi1.x, pc[u].x, wv.x);
            SWISH_ACC(a1, pi1.y, pc[u].y, wv.y);
            SWISH_ACC(a1, pi1.z, pc[u].z, wv.z);
            SWISH_ACC(a1, pi1.w, pc[u].w, wv.w);
            #pragma unroll
            for (int o = 16; o > 0; o >>= 1) {
                a0 += __shfl_xor_sync(0xffffffffu, a0, o);
                a1 += __shfl_xor_sync(0xffffffffu, a1, o);
            }
            if (lane == 0) {
                s_part[0][s0 + u][warp] = a0;
                s_part[1][s0 + u][warp] = a1;
            }
        }
    }
    __syncthreads();

    // ---- 8-way reduce: thread (tt,s) sums its 8 warp partials ----
    {
        const int tt = tid >> 7, s = tid & (Ss - 1);
        const float4* p = (const float4*)s_part[tt][s];
        const float4 q0 = p[0], q1 = p[1];
        s_sc[tt][s] = ((q0.x + q0.y) + (q0.z + q0.w))
                    + ((q1.x + q1.y) + (q1.z + q1.w));
    }
    __syncthreads();

    // ---- softmax: warp tt (<2) handles row tt ----
    if (warp < TG) {
        const int tt = warp;
        float v0 = s_sc[tt][lane];
        float v1 = s_sc[tt][lane + 32];
        float v2 = s_sc[tt][lane + 64];
        float v3 = s_sc[tt][lane + 96];
        float m = fmaxf(fmaxf(v0, v1), fmaxf(v2, v3));
        #pragma unroll
        for (int o = 16; o > 0; o >>= 1)
            m = fmaxf(m, __shfl_xor_sync(0xffffffffu, m, o));
        float p0 = __expf(v0 - m), p1 = __expf(v1 - m);
        float p2 = __expf(v2 - m), p3 = __expf(v3 - m);
        float sum = p0 + p1 + p2 + p3;
        #pragma unroll
        for (int o = 16; o > 0; o >>= 1)
            sum += __shfl_xor_sync(0xffffffffu, sum, o);
        const float inv = __fdividef(1.f, sum);
        const int tb = (tg * TG + tt) * Bb + b;
        float* attn_out = out + (size_t)Tt * Bb * Dd + (size_t)tb * Ss;
        p0 *= inv; p1 *= inv; p2 *= inv; p3 *= inv;
        s_sc[tt][lane]      = p0;  attn_out[lane]      = p0;
        s_sc[tt][lane + 32] = p1;  attn_out[lane + 32] = p1;
        s_sc[tt][lane + 64] = p2;  attn_out[lane + 64] = p2;
        s_sc[tt][lane + 96] = p3;  attn_out[lane + 96] = p3;
    }
    __syncthreads();

    // ---- attn_context[t,b,:] = sum_s attn[t,s] * context[b,s,:] ----
    const float4* ctx4 = (const float4*)(context + (size_t)b * Ss * Dd);
    float4 acc0 = make_float4(0.f, 0.f, 0.f, 0.f);
    float4 acc1 = make_float4(0.f, 0.f, 0.f, 0.f);

    #pragma unroll 4
    for (int s = 0; s < Ss; s++) {
        const float4 c = ctx4[(size_t)s * (Dd / 4) + tid];
        const float a0 = s_sc[0][s];
        const float a1 = s_sc[1][s];
        acc0.x = fmaf(a0, c.x, acc0.x);  acc0.y = fmaf(a0, c.y, acc0.y);
        acc0.z = fmaf(a0, c.z, acc0.z);  acc0.w = fmaf(a0, c.w, acc0.w);
        acc1.x = fmaf(a1, c.x, acc1.x);  acc1.y = fmaf(a1, c.y, acc1.y);
        acc1.z = fmaf(a1, c.z, acc1.z);  acc1.w = fmaf(a1, c.w, acc1.w);
    }
    ((float4*)(out + (size_t)tb0 * Dd))[tid] = acc0;
    ((float4*)(out + (size_t)tb1 * Dd))[tid] = acc1;
}

// ===========================================================================
extern "C" void kernel_launch(void* const* d_in, const int* in_sizes, int n_in,
                              void* d_out, int out_size) {
    const float* inputs  = (const float*)d_in[0];
    const float* context = (const float*)d_in[1];
    const float* W_in    = (const float*)d_in[2];
    const float* b_in    = (const float*)d_in[3];
    const float* W_ctx   = (const float*)d_in[4];
    const float* b_ctx   = (const float*)d_in[5];
    const float* w_one   = (const float*)d_in[6];
    // d_in[7] = b_one: softmax is shift-invariant -> no effect on outputs.
    float* out = (float*)d_out;

    gemm_kernel<<<320, 256>>>(inputs, context, W_in, b_in, W_ctx, b_ctx);
    attn_kernel<<<Bb * (Tt / TG), 256>>>(context, w_one, out);
}

// round 9
// speedup vs baseline: 1.3476x; 1.2037x over previous
#include <cuda_runtime.h>
#include <cuda_fp16.h>
#include <cstdint>

// Shapes (fixed by the problem)
#define Dd 1024
#define Tt 32
#define Bb 16
#define Ss 128
#define TG 2            // t-values per attn CTA (grid = 256)

// Scratch for the two projection GEMMs
__device__ float g_pi[Tt * Bb * Dd];   // [T*B, D]
__device__ float g_pc[Bb * Ss * Dd];   // [B*S, D]

// ===========================================================================
// Helpers
// ===========================================================================
__device__ __forceinline__ uint32_t smem_to_u32(const void* p) {
    uint32_t a;
    asm("{ .reg .u64 t; cvta.to.shared.u64 t, %1; cvt.u32.u64 %0, t; }" : "=r"(a) : "l"(p));
    return a;
}
__device__ __forceinline__ void ldsm_x4(uint32_t* r, uint32_t addr) {
    asm volatile("ldmatrix.sync.aligned.m8n8.x4.shared.b16 {%0,%1,%2,%3}, [%4];"
                 : "=r"(r[0]), "=r"(r[1]), "=r"(r[2]), "=r"(r[3]) : "r"(addr));
}
__device__ __forceinline__ void mma_f16(float* c, const uint32_t* a,
                                        uint32_t b0, uint32_t b1) {
    asm volatile(
        "mma.sync.aligned.m16n8k16.row.col.f32.f16.f16.f32 "
        "{%0,%1,%2,%3}, {%4,%5,%6,%7}, {%8,%9}, {%0,%1,%2,%3};"
        : "+f"(c[0]), "+f"(c[1]), "+f"(c[2]), "+f"(c[3])
        : "r"(a[0]), "r"(a[1]), "r"(a[2]), "r"(a[3]), "r"(b0), "r"(b1));
}
__device__ __forceinline__ uint32_t h2bits(__half2 h) {
    uint32_t r; __builtin_memcpy(&r, &h, 4); return r;
}
// A: split into fp16 hi + fp16 residual (hi+lo represents A to ~2^-22)
__device__ __forceinline__ void split_store16(float4 v, char* hp, char* lp) {
    __half hx = __float2half_rn(v.x), hy = __float2half_rn(v.y);
    __half hz = __float2half_rn(v.z), hw = __float2half_rn(v.w);
    float lx = v.x - __half2float(hx), ly = v.y - __half2float(hy);
    float lz = v.z - __half2float(hz), lw = v.w - __half2float(hw);
    uint2 h = make_uint2(h2bits(__halves2half2(hx, hy)), h2bits(__halves2half2(hz, hw)));
    uint2 l = make_uint2(h2bits(__halves2half2(__float2half_rn(lx), __float2half_rn(ly))),
                         h2bits(__halves2half2(__float2half_rn(lz), __float2half_rn(lw))));
    *(uint2*)hp = h;
    *(uint2*)lp = l;
}
// B: single fp16 rounding only
__device__ __forceinline__ void store_hi16(float4 v, char* hp) {
    __half hx = __float2half_rn(v.x), hy = __float2half_rn(v.y);
    __half hz = __float2half_rn(v.z), hw = __float2half_rn(v.w);
    *(uint2*)hp = make_uint2(h2bits(__halves2half2(hx, hy)),
                             h2bits(__halves2half2(hz, hw)));
}
__device__ __forceinline__ uint32_t swz(uint32_t off) {      // SW128 swizzle
    return off ^ ((off >> 3) & 0x70);
}

// ===========================================================================
// fp16 2-MMA split GEMM, double-buffered:
//   C[m,n] = sum_k A[m,k]*W[n,k] + bias[n]
//   A = Ah + Al (fp16 pair, ~2^-22 accurate); B = Bh (fp16, ~2^-11)
//   C ~= Ah*Bh + Al*Bh   (fp32 accum)  -> 2/3 the MMA count of 3-split.
// BM=128, BN=64, KC=32. 256 threads = 8 warps (4m x 2n), warp tile 32x32.
// smem rows 128B SW128-swizzled: A hi bytes [0,64), lo [64,128); B hi only.
// Per warp-chunk: 12 ldsm + 32 MMA; one __syncthreads per chunk.
// Grid: blocks [0,64) -> pi (M=512), [64,320) -> pc (M=2048).
// ===========================================================================
#define BMt 128
#define BNt 64
#define KC  32
#define NCHUNK (Dd / KC)        // 32

__global__ void __launch_bounds__(256, 2) gemm_kernel(
    const float* __restrict__ inputs, const float* __restrict__ context,
    const float* __restrict__ W_in,  const float* __restrict__ b_in,
    const float* __restrict__ W_ctx, const float* __restrict__ b_ctx)
{
    __shared__ __align__(1024) char sbuf[2][24576];   // [stage]: A 16384 | B 8192

    const int tid  = threadIdx.x;
    const int wid  = tid >> 5;
    const int lane = tid & 31;

    const float* A; const float* W; const float* bias; float* Cout; int tile;
    if (blockIdx.x < 64) { A = inputs;  W = W_in;  bias = b_in;  Cout = g_pi; tile = blockIdx.x; }
    else                 { A = context; W = W_ctx; bias = b_ctx; Cout = g_pc; tile = blockIdx.x - 64; }
    const int bm = (tile >> 4) * BMt;
    const int bn = (tile & 15) * BNt;

    const int warp_m = wid & 3;
    const int warp_n = wid >> 2;

    const float* aP[4]; uint32_t aHi[4];
    #pragma unroll
    for (int i = 0; i < 4; i++) {
        const int e = i * 256 + tid;
        aP[i]  = A + (size_t)(bm + (e >> 3)) * Dd + (e & 7) * 4;
        aHi[i] = (uint32_t)((e >> 3) * 128 + (e & 7) * 8);
    }
    const float* bP[2]; uint32_t bHi[2];
    #pragma unroll
    for (int i = 0; i < 2; i++) {
        const int e = i * 256 + tid;
        bP[i]  = W + (size_t)(bn + (e >> 3)) * Dd + (e & 7) * 4;
        bHi[i] = (uint32_t)((e >> 3) * 128 + (e & 7) * 8);
    }

    const int lr  = lane & 7;
    const int grp = lane >> 3;
    const uint32_t rowA0 = (uint32_t)(warp_m * 32 + (grp & 1) * 8 + lr) * 128;
    const uint32_t colA  = (uint32_t)((grp >> 1) * 16);
    const uint32_t rowB0 = (uint32_t)(warp_n * 32 + (grp >> 1) * 8 + lr) * 128;
    const uint32_t colB  = (uint32_t)((grp & 1) * 16);

    float acc[2][4][4];
    #pragma unroll
    for (int mi = 0; mi < 2; mi++)
        #pragma unroll
        for (int ni = 0; ni < 4; ni++)
            #pragma unroll
            for (int j = 0; j < 4; j++) acc[mi][ni][j] = 0.f;

    // prologue: chunk 0 -> stage 0
    float4 ra[4], rb[2];
    #pragma unroll
    for (int i = 0; i < 4; i++) ra[i] = *(const float4*)aP[i];
    #pragma unroll
    for (int i = 0; i < 2; i++) rb[i] = *(const float4*)bP[i];
    #pragma unroll
    for (int i = 0; i < 4; i++)
        split_store16(ra[i], sbuf[0] + swz(aHi[i]), sbuf[0] + swz(aHi[i] + 64));
    #pragma unroll
    for (int i = 0; i < 2; i++)
        store_hi16(rb[i], sbuf[0] + 16384 + swz(bHi[i]));
    __syncthreads();

    for (int c = 0; c < NCHUNK; c++) {
        const int cur = c & 1, nxt = cur ^ 1;

        if (c + 1 < NCHUNK) {
            const int kb = (c + 1) * KC;
            #pragma unroll
            for (int i = 0; i < 4; i++) ra[i] = *(const float4*)(aP[i] + kb);
            #pragma unroll
            for (int i = 0; i < 2; i++) rb[i] = *(const float4*)(bP[i] + kb);
        }

        const uint32_t baseA = smem_to_u32(sbuf[cur]);
        const uint32_t baseB = baseA + 16384;
        #pragma unroll
        for (int ks = 0; ks < 2; ks++) {
            const uint32_t kOff = (uint32_t)(ks * 32);
            uint32_t ah[2][4], al[2][4], bh[2][4];
            #pragma unroll
            for (int mi = 0; mi < 2; mi++) {
                const uint32_t r = rowA0 + (uint32_t)(mi * 16 * 128);
                ldsm_x4(ah[mi], baseA + swz(r + kOff + colA));
                ldsm_x4(al[mi], baseA + swz(r + 64 + kOff + colA));
            }
            #pragma unroll
            for (int ng = 0; ng < 2; ng++) {
                const uint32_t r = rowB0 + (uint32_t)(ng * 16 * 128);
                ldsm_x4(bh[ng], baseB + swz(r + kOff + colB));
            }
            #pragma unroll
            for (int mi = 0; mi < 2; mi++)
                #pragma unroll
                for (int ni = 0; ni < 4; ni++) {
                    const int ng = ni >> 1, sel = (ni & 1) * 2;
                    mma_f16(acc[mi][ni], ah[mi], bh[ng][sel], bh[ng][sel + 1]);
                    mma_f16(acc[mi][ni], al[mi], bh[ng][sel], bh[ng][sel + 1]);
                }
        }

        if (c + 1 < NCHUNK) {
            #pragma unroll
            for (int i = 0; i < 4; i++)
                split_store16(ra[i], sbuf[nxt] + swz(aHi[i]), sbuf[nxt] + swz(aHi[i] + 64));
            #pragma unroll
            for (int i = 0; i < 2; i++)
                store_hi16(rb[i], sbuf[nxt] + 16384 + swz(bHi[i]));
        }
        __syncthreads();
    }

    // epilogue: bias add + store
    const int tq = lane >> 2;
    const int tr = lane & 3;
    #pragma unroll
    for (int mi = 0; mi < 2; mi++)
        #pragma unroll
        for (int ni = 0; ni < 4; ni++) {
            const int col  = bn + warp_n * 32 + ni * 8 + tr * 2;
            const int row0 = bm + warp_m * 32 + mi * 16 + tq;
            const float2 bv = *(const float2*)(bias + col);
            float2 o0, o1;
            o0.x = acc[mi][ni][0] + bv.x;  o0.y = acc[mi][ni][1] + bv.y;
            o1.x = acc[mi][ni][2] + bv.x;  o1.y = acc[mi][ni][3] + bv.y;
            *(float2*)(Cout + (size_t)row0 * Dd + col)       = o0;
            *(float2*)(Cout + (size_t)(row0 + 8) * Dd + col) = o1;
        }
}

// ===========================================================================
// Fused scores -> softmax -> weighted context sum.
// R7 loop structure (warp-per-s: only 16 shuffle-reduces per warp) with
// pi held in REGISTERS (64 regs) and w in smem -> score inner iteration is
// 1 LDG (pc) + 1 LDS (w) per 8 swish-evals.  TG=2, 256 thr, grid 256,
// __launch_bounds__(256,2) -> 2 CTAs/SM.
// ===========================================================================
#define SWISH_ACC(accv, pic, pcc, wc)                                    \
    {                                                                    \
        float c_ = (pic) + (pcc);                                        \
        float h_ = 0.5f * c_;                                            \
        float th_;                                                       \
        asm("tanh.approx.f32 %0, %1;" : "=f"(th_) : "f"(h_));            \
        (accv) = fmaf(fmaf(th_, h_, h_), (wc), (accv));                  \
    }

__global__ void __launch_bounds__(256, 2) attn_kernel(
    const float* __restrict__ context,
    const float* __restrict__ w_one,
    float* __restrict__ out)
{
    const int b  = blockIdx.x & (Bb - 1);
    const int tg = blockIdx.x >> 4;          // 0..15 ; t = tg*2 + tt

    __shared__ __align__(16) float4 s_w[Dd / 4];
    __shared__ float s_sc[TG][Ss];

    const int tid  = threadIdx.x;
    const int lane = tid & 31;
    const int warp = tid >> 5;               // 0..7

    const int tb0 = (tg * TG + 0) * Bb + b;
    const int tb1 = tb0 + Bb;

    s_w[tid] = ((const float4*)w_one)[tid];

    // pi for both t's, this lane's d-slice {i*32+lane}, in registers
    float4 rp0[8], rp1[8];
    #pragma unroll
    for (int i = 0; i < 8; i++) {
        rp0[i] = ((const float4*)g_pi)[(size_t)tb0 * (Dd / 4) + i * 32 + lane];
        rp1[i] = ((const float4*)g_pi)[(size_t)tb1 * (Dd / 4) + i * 32 + lane];
    }
    __syncthreads();

    // ---- scores: warp handles s = warp, warp+8, ... ----
    const float4* pcb = (const float4*)g_pc + (size_t)b * Ss * (Dd / 4);
    for (int s = warp; s < Ss; s += 8) {
        const float4* row = pcb + (size_t)s * (Dd / 4);
        float a0 = 0.f, a1 = 0.f;
        #pragma unroll
        for (int i = 0; i < 8; i++) {
            const int idx = i * 32 + lane;
            const float4 pcv = row[idx];
            const float4 wv  = s_w[idx];
            SWISH_ACC(a0, rp0[i].x, pcv.x, wv.x);
            SWISH_ACC(a0, rp0[i].y, pcv.y, wv.y);
            SWISH_ACC(a0, rp0[i].z, pcv.z, wv.z);
            SWISH_ACC(a0, rp0[i].w, pcv.w, wv.w);
            SWISH_ACC(a1, rp1[i].x, pcv.x, wv.x);
            SWISH_ACC(a1, rp1[i].y, pcv.y, wv.y);
            SWISH_ACC(a1, rp1[i].z, pcv.z, wv.z);
            SWISH_ACC(a1, rp1[i].w, pcv.w, wv.w);
        }
        #pragma unroll
        for (int o = 16; o > 0; o >>= 1) {
            a0 += __shfl_xor_sync(0xffffffffu, a0, o);
            a1 += __shfl_xor_sync(0xffffffffu, a1, o);
        }
        if (lane == 0) { s_sc[0][s] = a0; s_sc[1][s] = a1; }
    }
    __syncthreads();

    // ---- softmax: warp tt (<2) handles row tt ----
    if (warp < TG) {
        const int tt = warp;
        float v0 = s_sc[tt][lane];
        float v1 = s_sc[tt][lane + 32];
        float v2 = s_sc[tt][lane + 64];
        float v3 = s_sc[tt][lane + 96];
        float m = fmaxf(fmaxf(v0, v1), fmaxf(v2, v3));
        #pragma unroll
        for (int o = 16; o > 0; o >>= 1)
            m = fmaxf(m, __shfl_xor_sync(0xffffffffu, m, o));
        float p0 = __expf(v0 - m), p1 = __expf(v1 - m);
        float p2 = __expf(v2 - m), p3 = __expf(v3 - m);
        float sum = p0 + p1 + p2 + p3;
        #pragma unroll
        for (int o = 16; o > 0; o >>= 1)
            sum += __shfl_xor_sync(0xffffffffu, sum, o);
        const float inv = __fdividef(1.f, sum);
        const int tb = (tg * TG + tt) * Bb + b;
        float* attn_out = out + (size_t)Tt * Bb * Dd + (size_t)tb * Ss;
        p0 *= inv; p1 *= inv; p2 *= inv; p3 *= inv;
        s_sc[tt][lane]      = p0;  attn_out[lane]      = p0;
        s_sc[tt][lane + 32] = p1;  attn_out[lane + 32] = p1;
        s_sc[tt][lane + 64] = p2;  attn_out[lane + 64] = p2;
        s_sc[tt][lane + 96] = p3;  attn_out[lane + 96] = p3;
    }
    __syncthreads();

    // ---- attn_context[t,b,:] = sum_s attn[t,s] * context[b,s,:] ----
    const float4* ctx4 = (const float4*)(context + (size_t)b * Ss * Dd);
    float4 acc0 = make_float4(0.f, 0.f, 0.f, 0.f);
    float4 acc1 = make_float4(0.f, 0.f, 0.f, 0.f);

    #pragma unroll 4
    for (int s = 0; s < Ss; s++) {
        const float4 c = ctx4[(size_t)s * (Dd / 4) + tid];
        const float a0 = s_sc[0][s];
        const float a1 = s_sc[1][s];
        acc0.x = fmaf(a0, c.x, acc0.x);  acc0.y = fmaf(a0, c.y, acc0.y);
        acc0.z = fmaf(a0, c.z, acc0.z);  acc0.w = fmaf(a0, c.w, acc0.w);
        acc1.x = fmaf(a1, c.x, acc1.x);  acc1.y = fmaf(a1, c.y, acc1.y);
        acc1.z = fmaf(a1, c.z, acc1.z);  acc1.w = fmaf(a1, c.w, acc1.w);
    }
    ((float4*)(out + (size_t)tb0 * Dd))[tid] = acc0;
    ((float4*)(out + (size_t)tb1 * Dd))[tid] = acc1;
}

// ===========================================================================
extern "C" void kernel_launch(void* const* d_in, const int* in_sizes, int n_in,
                              void* d_out, int out_size) {
    const float* inputs  = (const float*)d_in[0];
    const float* context = (const float*)d_in[1];
    const float* W_in    = (const float*)d_in[2];
    const float* b_in    = (const float*)d_in[3];
    const float* W_ctx   = (const float*)d_in[4];
    const float* b_ctx   = (const float*)d_in[5];
    const float* w_one   = (const float*)d_in[6];
    // d_in[7] = b_one: softmax is shift-invariant -> no effect on outputs.
    float* out = (float*)d_out;

    gemm_kernel<<<320, 256>>>(inputs, context, W_in, b_in, W_ctx, b_ctx);
    attn_kernel<<<Bb * (Tt / TG), 256>>>(context, w_one, out);
}

// round 10
// speedup vs baseline: 1.6321x; 1.2111x over previous
#include <cuda_runtime.h>
#include <cuda_fp16.h>
#include <cstdint>

// Shapes (fixed by the problem)
#define Dd 1024
#define Tt 32
#define Bb 16
#define Ss 128
#define TG 2            // t-values per attn CTA (grid = 256)

// Scratch for the two projection GEMMs
__device__ float g_pi[Tt * Bb * Dd];   // [T*B, D]
__device__ float g_pc[Bb * Ss * Dd];   // [B*S, D]

// ===========================================================================
// Helpers
// ===========================================================================
__device__ __forceinline__ uint32_t smem_to_u32(const void* p) {
    uint32_t a;
    asm("{ .reg .u64 t; cvta.to.shared.u64 t, %1; cvt.u32.u64 %0, t; }" : "=r"(a) : "l"(p));
    return a;
}
__device__ __forceinline__ void ldsm_x4(uint32_t* r, uint32_t addr) {
    asm volatile("ldmatrix.sync.aligned.m8n8.x4.shared.b16 {%0,%1,%2,%3}, [%4];"
                 : "=r"(r[0]), "=r"(r[1]), "=r"(r[2]), "=r"(r[3]) : "r"(addr));
}
__device__ __forceinline__ void mma_f16(float* c, const uint32_t* a,
                                        uint32_t b0, uint32_t b1) {
    asm volatile(
        "mma.sync.aligned.m16n8k16.row.col.f32.f16.f16.f32 "
        "{%0,%1,%2,%3}, {%4,%5,%6,%7}, {%8,%9}, {%0,%1,%2,%3};"
        : "+f"(c[0]), "+f"(c[1]), "+f"(c[2]), "+f"(c[3])
        : "r"(a[0]), "r"(a[1]), "r"(a[2]), "r"(a[3]), "r"(b0), "r"(b1));
}
__device__ __forceinline__ uint32_t h2bits(__half2 h) {
    uint32_t r; __builtin_memcpy(&r, &h, 4); return r;
}
// round float4 to fp16x4 and store (8 bytes)
__device__ __forceinline__ void store_hi16(float4 v, char* hp) {
    __half hx = __float2half_rn(v.x), hy = __float2half_rn(v.y);
    __half hz = __float2half_rn(v.z), hw = __float2half_rn(v.w);
    *(uint2*)hp = make_uint2(h2bits(__halves2half2(hx, hy)),
                             h2bits(__halves2half2(hz, hw)));
}
__device__ __forceinline__ uint32_t swz(uint32_t off) {      // SW128 swizzle
    return off ^ ((off >> 3) & 0x70);
}

// ===========================================================================
// fp16 single-MMA GEMM, double-buffered:
//   C[m,n] = sum_k fp16(A[m,k]) * fp16(W[n,k]) + bias[n]   (fp32 accum)
// BM=128, BN=64, KC=32. 256 threads = 8 warps (4m x 2n), warp tile 32x32.
// smem rows 128B SW128-swizzled; fp16 data occupies bytes [0,64) of each row
// (the [64,128) halves, formerly the residual plane, are unused).
// Per warp-chunk: 8 ldsm + 16 MMA; one __syncthreads per chunk.
// Grid: blocks [0,64) -> pi (M=512), [64,320) -> pc (M=2048).
// ===========================================================================
#define BMt 128
#define BNt 64
#define KC  32
#define NCHUNK (Dd / KC)        // 32

__global__ void __launch_bounds__(256, 2) gemm_kernel(
    const float* __restrict__ inputs, const float* __restrict__ context,
    const float* __restrict__ W_in,  const float* __restrict__ b_in,
    const float* __restrict__ W_ctx, const float* __restrict__ b_ctx)
{
    __shared__ __align__(1024) char sbuf[2][24576];   // [stage]: A 16384 | B 8192

    const int tid  = threadIdx.x;
    const int wid  = tid >> 5;
    const int lane = tid & 31;

    const float* A; const float* W; const float* bias; float* Cout; int tile;
    if (blockIdx.x < 64) { A = inputs;  W = W_in;  bias = b_in;  Cout = g_pi; tile = blockIdx.x; }
    else                 { A = context; W = W_ctx; bias = b_ctx; Cout = g_pc; tile = blockIdx.x - 64; }
    const int bm = (tile >> 4) * BMt;
    const int bn = (tile & 15) * BNt;

    const int warp_m = wid & 3;
    const int warp_n = wid >> 2;

    const float* aP[4]; uint32_t aHi[4];
    #pragma unroll
    for (int i = 0; i < 4; i++) {
        const int e = i * 256 + tid;
        aP[i]  = A + (size_t)(bm + (e >> 3)) * Dd + (e & 7) * 4;
        aHi[i] = (uint32_t)((e >> 3) * 128 + (e & 7) * 8);
    }
    const float* bP[2]; uint32_t bHi[2];
    #pragma unroll
    for (int i = 0; i < 2; i++) {
        const int e = i * 256 + tid;
        bP[i]  = W + (size_t)(bn + (e >> 3)) * Dd + (e & 7) * 4;
        bHi[i] = (uint32_t)((e >> 3) * 128 + (e & 7) * 8);
    }

    const int lr  = lane & 7;
    const int grp = lane >> 3;
    const uint32_t rowA0 = (uint32_t)(warp_m * 32 + (grp & 1) * 8 + lr) * 128;
    const uint32_t colA  = (uint32_t)((grp >> 1) * 16);
    const uint32_t rowB0 = (uint32_t)(warp_n * 32 + (grp >> 1) * 8 + lr) * 128;
    const uint32_t colB  = (uint32_t)((grp & 1) * 16);

    float acc[2][4][4];
    #pragma unroll
    for (int mi = 0; mi < 2; mi++)
        #pragma unroll
        for (int ni = 0; ni < 4; ni++)
            #pragma unroll
            for (int j = 0; j < 4; j++) acc[mi][ni][j] = 0.f;

    // prologue: chunk 0 -> stage 0
    float4 ra[4], rb[2];
    #pragma unroll
    for (int i = 0; i < 4; i++) ra[i] = *(const float4*)aP[i];
    #pragma unroll
    for (int i = 0; i < 2; i++) rb[i] = *(const float4*)bP[i];
    #pragma unroll
    for (int i = 0; i < 4; i++)
        store_hi16(ra[i], sbuf[0] + swz(aHi[i]));
    #pragma unroll
    for (int i = 0; i < 2; i++)
        store_hi16(rb[i], sbuf[0] + 16384 + swz(bHi[i]));
    __syncthreads();

    for (int c = 0; c < NCHUNK; c++) {
        const int cur = c & 1, nxt = cur ^ 1;

        if (c + 1 < NCHUNK) {
            const int kb = (c + 1) * KC;
            #pragma unroll
            for (int i = 0; i < 4; i++) ra[i] = *(const float4*)(aP[i] + kb);
            #pragma unroll
            for (int i = 0; i < 2; i++) rb[i] = *(const float4*)(bP[i] + kb);
        }

        const uint32_t baseA = smem_to_u32(sbuf[cur]);
        const uint32_t baseB = baseA + 16384;
        #pragma unroll
        for (int ks = 0; ks < 2; ks++) {
            const uint32_t kOff = (uint32_t)(ks * 32);
            uint32_t ah[2][4], bh[2][4];
            #pragma unroll
            for (int mi = 0; mi < 2; mi++) {
                const uint32_t r = rowA0 + (uint32_t)(mi * 16 * 128);
                ldsm_x4(ah[mi], baseA + swz(r + kOff + colA));
            }
            #pragma unroll
            for (int ng = 0; ng < 2; ng++) {
                const uint32_t r = rowB0 + (uint32_t)(ng * 16 * 128);
                ldsm_x4(bh[ng], baseB + swz(r + kOff + colB));
            }
            #pragma unroll
            for (int mi = 0; mi < 2; mi++)
                #pragma unroll
                for (int ni = 0; ni < 4; ni++) {
                    const int ng = ni >> 1, sel = (ni & 1) * 2;
                    mma_f16(acc[mi][ni], ah[mi], bh[ng][sel], bh[ng][sel + 1]);
                }
        }

        if (c + 1 < NCHUNK) {
            #pragma unroll
            for (int i = 0; i < 4; i++)
                store_hi16(ra[i], sbuf[nxt] + swz(aHi[i]));
            #pragma unroll
            for (int i = 0; i < 2; i++)
                store_hi16(rb[i], sbuf[nxt] + 16384 + swz(bHi[i]));
        }
        __syncthreads();
    }

    // epilogue: bias add + store
    const int tq = lane >> 2;
    const int tr = lane & 3;
    #pragma unroll
    for (int mi = 0; mi < 2; mi++)
        #pragma unroll
        for (int ni = 0; ni < 4; ni++) {
            const int col  = bn + warp_n * 32 + ni * 8 + tr * 2;
            const int row0 = bm + warp_m * 32 + mi * 16 + tq;
            const float2 bv = *(const float2*)(bias + col);
            float2 o0, o1;
            o0.x = acc[mi][ni][0] + bv.x;  o0.y = acc[mi][ni][1] + bv.y;
            o1.x = acc[mi][ni][2] + bv.x;  o1.y = acc[mi][ni][3] + bv.y;
            *(float2*)(Cout + (size_t)row0 * Dd + col)       = o0;
            *(float2*)(Cout + (size_t)(row0 + 8) * Dd + col) = o1;
        }
}

// ===========================================================================
// Fused scores -> softmax -> weighted context sum (UNCHANGED from R9, 45.3us).
// ===========================================================================
#define SWISH_ACC(accv, pic, pcc, wc)                                    \
    {                                                                    \
        float c_ = (pic) + (pcc);                                        \
        float h_ = 0.5f * c_;                                            \
        float th_;                                                       \
        asm("tanh.approx.f32 %0, %1;" : "=f"(th_) : "f"(h_));            \
        (accv) = fmaf(fmaf(th_, h_, h_), (wc), (accv));                  \
    }

__global__ void __launch_bounds__(256, 2) attn_kernel(
    const float* __restrict__ context,
    const float* __restrict__ w_one,
    float* __restrict__ out)
{
    const int b  = blockIdx.x & (Bb - 1);
    const int tg = blockIdx.x >> 4;          // 0..15 ; t = tg*2 + tt

    __shared__ __align__(16) float4 s_w[Dd / 4];
    __shared__ float s_sc[TG][Ss];

    const int tid  = threadIdx.x;
    const int lane = tid & 31;
    const int warp = tid >> 5;               // 0..7

    const int tb0 = (tg * TG + 0) * Bb + b;
    const int tb1 = tb0 + Bb;

    s_w[tid] = ((const float4*)w_one)[tid];

    // pi for both t's, this lane's d-slice {i*32+lane}, in registers
    float4 rp0[8], rp1[8];
    #pragma unroll
    for (int i = 0; i < 8; i++) {
        rp0[i] = ((const float4*)g_pi)[(size_t)tb0 * (Dd / 4) + i * 32 + lane];
        rp1[i] = ((const float4*)g_pi)[(size_t)tb1 * (Dd / 4) + i * 32 + lane];
    }
    __syncthreads();

    // ---- scores: warp handles s = warp, warp+8, ... ----
    const float4* pcb = (const float4*)g_pc + (size_t)b * Ss * (Dd / 4);
    for (int s = warp; s < Ss; s += 8) {
        const float4* row = pcb + (size_t)s * (Dd / 4);
        float a0 = 0.f, a1 = 0.f;
        #pragma unroll
        for (int i = 0; i < 8; i++) {
            const int idx = i * 32 + lane;
            const float4 pcv = row[idx];
            const float4 wv  = s_w[idx];
            SWISH_ACC(a0, rp0[i].x, pcv.x, wv.x);
            SWISH_ACC(a0, rp0[i].y, pcv.y, wv.y);
            SWISH_ACC(a0, rp0[i].z, pcv.z, wv.z);
            SWISH_ACC(a0, rp0[i].w, pcv.w, wv.w);
            SWISH_ACC(a1, rp1[i].x, pcv.x, wv.x);
            SWISH_ACC(a1, rp1[i].y, pcv.y, wv.y);
            SWISH_ACC(a1, rp1[i].z, pcv.z, wv.z);
            SWISH_ACC(a1, rp1[i].w, pcv.w, wv.w);
        }
        #pragma unroll
        for (int o = 16; o > 0; o >>= 1) {
            a0 += __shfl_xor_sync(0xffffffffu, a0, o);
            a1 += __shfl_xor_sync(0xffffffffu, a1, o);
        }
        if (lane == 0) { s_sc[0][s] = a0; s_sc[1][s] = a1; }
    }
    __syncthreads();

    // ---- softmax: warp tt (<2) handles row tt ----
    if (warp < TG) {
        const int tt = warp;
        float v0 = s_sc[tt][lane];
        float v1 = s_sc[tt][lane + 32];
        float v2 = s_sc[tt][lane + 64];
        float v3 = s_sc[tt][lane + 96];
        float m = fmaxf(fmaxf(v0, v1), fmaxf(v2, v3));
        #pragma unroll
        for (int o = 16; o > 0; o >>= 1)
            m = fmaxf(m, __shfl_xor_sync(0xffffffffu, m, o));
        float p0 = __expf(v0 - m), p1 = __expf(v1 - m);
        float p2 = __expf(v2 - m), p3 = __expf(v3 - m);
        float sum = p0 + p1 + p2 + p3;
        #pragma unroll
        for (int o = 16; o > 0; o >>= 1)
            sum += __shfl_xor_sync(0xffffffffu, sum, o);
        const float inv = __fdividef(1.f, sum);
        const int tb = (tg * TG + tt) * Bb + b;
        float* attn_out = out + (size_t)Tt * Bb * Dd + (size_t)tb * Ss;
        p0 *= inv; p1 *= inv; p2 *= inv; p3 *= inv;
        s_sc[tt][lane]      = p0;  attn_out[lane]      = p0;
        s_sc[tt][lane + 32] = p1;  attn_out[lane + 32] = p1;
        s_sc[tt][lane + 64] = p2;  attn_out[lane + 64] = p2;
        s_sc[tt][lane + 96] = p3;  attn_out[lane + 96] = p3;
    }
    __syncthreads();

    // ---- attn_context[t,b,:] = sum_s attn[t,s] * context[b,s,:] ----
    const float4* ctx4 = (const float4*)(context + (size_t)b * Ss * Dd);
    float4 acc0 = make_float4(0.f, 0.f, 0.f, 0.f);
    float4 acc1 = make_float4(0.f, 0.f, 0.f, 0.f);

    #pragma unroll 4
    for (int s = 0; s < Ss; s++) {
        const float4 c = ctx4[(size_t)s * (Dd / 4) + tid];
        const float a0 = s_sc[0][s];
        const float a1 = s_sc[1][s];
        acc0.x = fmaf(a0, c.x, acc0.x);  acc0.y = fmaf(a0, c.y, acc0.y);
        acc0.z = fmaf(a0, c.z, acc0.z);  acc0.w = fmaf(a0, c.w, acc0.w);
        acc1.x = fmaf(a1, c.x, acc1.x);  acc1.y = fmaf(a1, c.y, acc1.y);
        acc1.z = fmaf(a1, c.z, acc1.z);  acc1.w = fmaf(a1, c.w, acc1.w);
    }
    ((float4*)(out + (size_t)tb0 * Dd))[tid] = acc0;
    ((float4*)(out + (size_t)tb1 * Dd))[tid] = acc1;
}

// ===========================================================================
extern "C" void kernel_launch(void* const* d_in, const int* in_sizes, int n_in,
                              void* d_out, int out_size) {
    const float* inputs  = (const float*)d_in[0];
    const float* context = (const float*)d_in[1];
    const float* W_in    = (const float*)d_in[2];
    const float* b_in    = (const float*)d_in[3];
    const float* W_ctx   = (const float*)d_in[4];
    const float* b_ctx   = (const float*)d_in[5];
    const float* w_one   = (const float*)d_in[6];
    // d_in[7] = b_one: softmax is shift-invariant -> no effect on outputs.
    float* out = (float*)d_out;

    gemm_kernel<<<320, 256>>>(inputs, context, W_in, b_in, W_ctx, b_ctx);
    attn_kernel<<<Bb * (Tt / TG), 256>>>(context, w_one, out);
}

// round 11
// speedup vs baseline: 1.6417x; 1.0059x over previous
#include <cuda_runtime.h>
#include <cuda_fp16.h>
#include <cstdint>

// Shapes (fixed by the problem)
#define Dd 1024
#define Tt 32
#define Bb 16
#define Ss 128
#define TG 2            // t-values per attn CTA (grid = 256)

// Scratch for the two projection GEMMs — fp16, PRE-SCALED BY 0.5:
//   g_pi[t,b,d] = 0.5*(inputs@W_in^T + b_in),  g_pc[b,s,d] = 0.5*(context@W_ctx^T + b_ctx)
// They feed ONLY the swish (h = c/2 is exactly what swish needs).
__device__ __half g_pi[Tt * Bb * Dd];
__device__ __half g_pc[Bb * Ss * Dd];

// ===========================================================================
// Helpers
// ===========================================================================
__device__ __forceinline__ uint32_t smem_to_u32(const void* p) {
    uint32_t a;
    asm("{ .reg .u64 t; cvta.to.shared.u64 t, %1; cvt.u32.u64 %0, t; }" : "=r"(a) : "l"(p));
    return a;
}
__device__ __forceinline__ void ldsm_x4(uint32_t* r, uint32_t addr) {
    asm volatile("ldmatrix.sync.aligned.m8n8.x4.shared.b16 {%0,%1,%2,%3}, [%4];"
                 : "=r"(r[0]), "=r"(r[1]), "=r"(r[2]), "=r"(r[3]) : "r"(addr));
}
__device__ __forceinline__ void mma_f16(float* c, const uint32_t* a,
                                        uint32_t b0, uint32_t b1) {
    asm volatile(
        "mma.sync.aligned.m16n8k16.row.col.f32.f16.f16.f32 "
        "{%0,%1,%2,%3}, {%4,%5,%6,%7}, {%8,%9}, {%0,%1,%2,%3};"
        : "+f"(c[0]), "+f"(c[1]), "+f"(c[2]), "+f"(c[3])
        : "r"(a[0]), "r"(a[1]), "r"(a[2]), "r"(a[3]), "r"(b0), "r"(b1));
}
__device__ __forceinline__ uint32_t h2bits(__half2 h) {
    uint32_t r; __builtin_memcpy(&r, &h, 4); return r;
}
__device__ __forceinline__ __half2 bits2h(uint32_t u) {
    __half2 h; __builtin_memcpy(&h, &u, 4); return h;
}
// round float4 to fp16x4 and store (8 bytes)
__device__ __forceinline__ void store_hi16(float4 v, char* hp) {
    __half hx = __float2half_rn(v.x), hy = __float2half_rn(v.y);
    __half hz = __float2half_rn(v.z), hw = __float2half_rn(v.w);
    *(uint2*)hp = make_uint2(h2bits(__halves2half2(hx, hy)),
                             h2bits(__halves2half2(hz, hw)));
}
__device__ __forceinline__ uint32_t swz(uint32_t off) {      // SW128 swizzle
    return off ^ ((off >> 3) & 0x70);
}

// packed swish on 2 elems: h2 = pi2+pc2 (already = c/2); sw = h + h*tanh(h);
// accumulate sw*w into fp32 accumulators.
__device__ __forceinline__ void swish2_acc(uint32_t piu, uint32_t pcu,
                                           float wx, float wy,
                                           float& ax, float& ay) {
    __half2 h2 = __hadd2(bits2h(piu), bits2h(pcu));
    uint32_t tu;
    asm("tanh.approx.f16x2 %0, %1;" : "=r"(tu) : "r"(h2bits(h2)));
    __half2 sw = __hfma2(bits2h(tu), h2, h2);
    float2 f = __half22float2(sw);
    ax = fmaf(f.x, wx, ax);
    ay = fmaf(f.y, wy, ay);
}

// ===========================================================================
// fp16 single-MMA GEMM, double-buffered (R10 structure; epilogue now stores
// fp16 * 0.5).  BM=128, BN=64, KC=32; 256 thr = 8 warps (4m x 2n).
// Grid: blocks [0,64) -> pi (M=512), [64,320) -> pc (M=2048).
// ===========================================================================
#define BMt 128
#define BNt 64
#define KC  32
#define NCHUNK (Dd / KC)        // 32

__global__ void __launch_bounds__(256, 2) gemm_kernel(
    const float* __restrict__ inputs, const float* __restrict__ context,
    const float* __restrict__ W_in,  const float* __restrict__ b_in,
    const float* __restrict__ W_ctx, const float* __restrict__ b_ctx)
{
    __shared__ __align__(1024) char sbuf[2][24576];   // [stage]: A 16384 | B 8192

    const int tid  = threadIdx.x;
    const int wid  = tid >> 5;
    const int lane = tid & 31;

    const float* A; const float* W; const float* bias; __half* Cout; int tile;
    if (blockIdx.x < 64) { A = inputs;  W = W_in;  bias = b_in;  Cout = g_pi; tile = blockIdx.x; }
    else                 { A = context; W = W_ctx; bias = b_ctx; Cout = g_pc; tile = blockIdx.x - 64; }
    const int bm = (tile >> 4) * BMt;
    const int bn = (tile & 15) * BNt;

    const int warp_m = wid & 3;
    const int warp_n = wid >> 2;

    const float* aP[4]; uint32_t aHi[4];
    #pragma unroll
    for (int i = 0; i < 4; i++) {
        const int e = i * 256 + tid;
        aP[i]  = A + (size_t)(bm + (e >> 3)) * Dd + (e & 7) * 4;
        aHi[i] = (uint32_t)((e >> 3) * 128 + (e & 7) * 8);
    }
    const float* bP[2]; uint32_t bHi[2];
    #pragma unroll
    for (int i = 0; i < 2; i++) {
        const int e = i * 256 + tid;
        bP[i]  = W + (size_t)(bn + (e >> 3)) * Dd + (e & 7) * 4;
        bHi[i] = (uint32_t)((e >> 3) * 128 + (e & 7) * 8);
    }

    const int lr  = lane & 7;
    const int grp = lane >> 3;
    const uint32_t rowA0 = (uint32_t)(warp_m * 32 + (grp & 1) * 8 + lr) * 128;
    const uint32_t colA  = (uint32_t)((grp >> 1) * 16);
    const uint32_t rowB0 = (uint32_t)(warp_n * 32 + (grp >> 1) * 8 + lr) * 128;
    const uint32_t colB  = (uint32_t)((grp & 1) * 16);

    float acc[2][4][4];
    #pragma unroll
    for (int mi = 0; mi < 2; mi++)
        #pragma unroll
        for (int ni = 0; ni < 4; ni++)
            #pragma unroll
            for (int j = 0; j < 4; j++) acc[mi][ni][j] = 0.f;

    // prologue: chunk 0 -> stage 0
    float4 ra[4], rb[2];
    #pragma unroll
    for (int i = 0; i < 4; i++) ra[i] = *(const float4*)aP[i];
    #pragma unroll
    for (int i = 0; i < 2; i++) rb[i] = *(const float4*)bP[i];
    #pragma unroll
    for (int i = 0; i < 4; i++)
        store_hi16(ra[i], sbuf[0] + swz(aHi[i]));
    #pragma unroll
    for (int i = 0; i < 2; i++)
        store_hi16(rb[i], sbuf[0] + 16384 + swz(bHi[i]));
    __syncthreads();

    for (int c = 0; c < NCHUNK; c++) {
        const int cur = c & 1, nxt = cur ^ 1;

        if (c + 1 < NCHUNK) {
            const int kb = (c + 1) * KC;
            #pragma unroll
            for (int i = 0; i < 4; i++) ra[i] = *(const float4*)(aP[i] + kb);
            #pragma unroll
            for (int i = 0; i < 2; i++) rb[i] = *(const float4*)(bP[i] + kb);
        }

        const uint32_t baseA = smem_to_u32(sbuf[cur]);
        const uint32_t baseB = baseA + 16384;
        #pragma unroll
        for (int ks = 0; ks < 2; ks++) {
            const uint32_t kOff = (uint32_t)(ks * 32);
            uint32_t ah[2][4], bh[2][4];
            #pragma unroll
            for (int mi = 0; mi < 2; mi++) {
                const uint32_t r = rowA0 + (uint32_t)(mi * 16 * 128);
                ldsm_x4(ah[mi], baseA + swz(r + kOff + colA));
            }
            #pragma unroll
            for (int ng = 0; ng < 2; ng++) {
                const uint32_t r = rowB0 + (uint32_t)(ng * 16 * 128);
                ldsm_x4(bh[ng], baseB + swz(r + kOff + colB));
            }
            #pragma unroll
            for (int mi = 0; mi < 2; mi++)
                #pragma unroll
                for (int ni = 0; ni < 4; ni++) {
                    const int ng = ni >> 1, sel = (ni & 1) * 2;
                    mma_f16(acc[mi][ni], ah[mi], bh[ng][sel], bh[ng][sel + 1]);
                }
        }

        if (c + 1 < NCHUNK) {
            #pragma unroll
            for (int i = 0; i < 4; i++)
                store_hi16(ra[i], sbuf[nxt] + swz(aHi[i]));
            #pragma unroll
            for (int i = 0; i < 2; i++)
                store_hi16(rb[i], sbuf[nxt] + 16384 + swz(bHi[i]));
        }
        __syncthreads();
    }

    // epilogue: bias add, scale by 0.5, pack to fp16
    const int tq = lane >> 2;
    const int tr = lane & 3;
    #pragma unroll
    for (int mi = 0; mi < 2; mi++)
        #pragma unroll
        for (int ni = 0; ni < 4; ni++) {
            const int col  = bn + warp_n * 32 + ni * 8 + tr * 2;
            const int row0 = bm + warp_m * 32 + mi * 16 + tq;
            const float2 bv = *(const float2*)(bias + col);
            __half2 h0 = __floats2half2_rn((acc[mi][ni][0] + bv.x) * 0.5f,
                                           (acc[mi][ni][1] + bv.y) * 0.5f);
            __half2 h1 = __floats2half2_rn((acc[mi][ni][2] + bv.x) * 0.5f,
                                           (acc[mi][ni][3] + bv.y) * 0.5f);
            *(__half2*)(Cout + (size_t)row0 * Dd + col)       = h0;
            *(__half2*)(Cout + (size_t)(row0 + 8) * Dd + col) = h1;
        }
}

// ===========================================================================
// Fused scores -> softmax -> weighted context sum.
// Score phase fully packed fp16x2: pi (both t's) + w_one in REGISTERS,
// pc loaded as uint4 (8 halves = 16B per lane per iter, 4 iters cover D).
// swish = h + h*tanh(h) via tanh.approx.f16x2; fp32 accumulate (4 accs/t).
// TG=2, 256 thr, grid 256, 2 CTAs/SM.
// ===========================================================================
__global__ void __launch_bounds__(256, 2) attn_kernel(
    const float* __restrict__ context,
    const float* __restrict__ w_one,
    float* __restrict__ out)
{
    const int b  = blockIdx.x & (Bb - 1);
    const int tg = blockIdx.x >> 4;          // 0..15 ; t = tg*2 + tt

    __shared__ float s_sc[TG][Ss];

    const int tid  = threadIdx.x;
    const int lane = tid & 31;
    const int warp = tid >> 5;               // 0..7

    const int tb0 = (tg * TG + 0) * Bb + b;
    const int tb1 = tb0 + Bb;

    // pi rows (half, = c/2) for both t's: 4 uint4 each (this lane's d-slice)
    // w_one: 8 float4 in registers (no smem in the score loop at all)
    uint4 rp0[4], rp1[4];
    float4 wA[4], wB[4];
    #pragma unroll
    for (int i = 0; i < 4; i++) {
        const int u = i * 32 + lane;         // uint4 index within a 128-uint4 row
        rp0[i] = ((const uint4*)g_pi)[(size_t)tb0 * 128 + u];
        rp1[i] = ((const uint4*)g_pi)[(size_t)tb1 * 128 + u];
        wA[i]  = ((const float4*)w_one)[u * 2];
        wB[i]  = ((const float4*)w_one)[u * 2 + 1];
    }

    // ---- scores: warp handles s = warp, warp+8, ... ----
    const uint4* pcb = (const uint4*)g_pc + (size_t)b * Ss * 128;
    for (int s = warp; s < Ss; s += 8) {
        const uint4* row = pcb + (size_t)s * 128;
        uint4 q[4];
        #pragma unroll
        for (int i = 0; i < 4; i++) q[i] = row[i * 32 + lane];

        float a0[4] = {0.f, 0.f, 0.f, 0.f};
        float a1[4] = {0.f, 0.f, 0.f, 0.f};
        #pragma unroll
        for (int i = 0; i < 4; i++) {
            swish2_acc(rp0[i].x, q[i].x, wA[i].x, wA[i].y, a0[0], a0[1]);
            swish2_acc(rp0[i].y, q[i].y, wA[i].z, wA[i].w, a0[2], a0[3]);
            swish2_acc(rp0[i].z, q[i].z, wB[i].x, wB[i].y, a0[0], a0[1]);
            swish2_acc(rp0[i].w, q[i].w, wB[i].z, wB[i].w, a0[2], a0[3]);
            swish2_acc(rp1[i].x, q[i].x, wA[i].x, wA[i].y, a1[0], a1[1]);
            swish2_acc(rp1[i].y, q[i].y, wA[i].z, wA[i].w, a1[2], a1[3]);
            swish2_acc(rp1[i].z, q[i].z, wB[i].x, wB[i].y, a1[0], a1[1]);
            swish2_acc(rp1[i].w, q[i].w, wB[i].z, wB[i].w, a1[2], a1[3]);
        }
        float s0 = (a0[0] + a0[1]) + (a0[2] + a0[3]);
        float s1 = (a1[0] + a1[1]) + (a1[2] + a1[3]);
        #pragma unroll
        for (int o = 16; o > 0; o >>= 1) {
            s0 += __shfl_xor_sync(0xffffffffu, s0, o);
            s1 += __shfl_xor_sync(0xffffffffu, s1, o);
        }
        if (lane == 0) { s_sc[0][s] = s0; s_sc[1][s] = s1; }
    }
    __syncthreads();

    // ---- softmax: warp tt (<2) handles row tt ----
    if (warp < TG) {
        const int tt = warp;
        float v0 = s_sc[tt][lane];
        float v1 = s_sc[tt][lane + 32];
        float v2 = s_sc[tt][lane + 64];
        float v3 = s_sc[tt][lane + 96];
        float m = fmaxf(fmaxf(v0, v1), fmaxf(v2, v3));
        #pragma unroll
        for (int o = 16; o > 0; o >>= 1)
            m = fmaxf(m, __shfl_xor_sync(0xffffffffu, m, o));
        float p0 = __expf(v0 - m), p1 = __expf(v1 - m);
        float p2 = __expf(v2 - m), p3 = __expf(v3 - m);
        float sum = p0 + p1 + p2 + p3;
        #pragma unroll
        for (int o = 16; o > 0; o >>= 1)
            sum += __shfl_xor_sync(0xffffffffu, sum, o);
        const float inv = __fdividef(1.f, sum);
        const int tb = (tg * TG + tt) * Bb + b;
        float* attn_out = out + (size_t)Tt * Bb * Dd + (size_t)tb * Ss;
        p0 *= inv; p1 *= inv; p2 *= inv; p3 *= inv;
        s_sc[tt][lane]      = p0;  attn_out[lane]      = p0;
        s_sc[tt][lane + 32] = p1;  attn_out[lane + 32] = p1;
        s_sc[tt][lane + 64] = p2;  attn_out[lane + 64] = p2;
        s_sc[tt][lane + 96] = p3;  attn_out[lane + 96] = p3;
    }
    __syncthreads();

    // ---- attn_context[t,b,:] = sum_s attn[t,s] * context[b,s,:] ----
    const float4* ctx4 = (const float4*)(context + (size_t)b * Ss * Dd);
    float4 acc0 = make_float4(0.f, 0.f, 0.f, 0.f);
    float4 acc1 = make_float4(0.f, 0.f, 0.f, 0.f);

    #pragma unroll 4
    for (int s = 0; s < Ss; s++) {
        const float4 c = ctx4[(size_t)s * (Dd / 4) + tid];
        const float a0 = s_sc[0][s];
        const float a1 = s_sc[1][s];
        acc0.x = fmaf(a0, c.x, acc0.x);  acc0.y = fmaf(a0, c.y, acc0.y);
        acc0.z = fmaf(a0, c.z, acc0.z);  acc0.w = fmaf(a0, c.w, acc0.w);
        acc1.x = fmaf(a1, c.x, acc1.x);  acc1.y = fmaf(a1, c.y, acc1.y);
        acc1.z = fmaf(a1, c.z, acc1.z);  acc1.w = fmaf(a1, c.w, acc1.w);
    }
    ((float4*)(out + (size_t)tb0 * Dd))[tid] = acc0;
    ((float4*)(out + (size_t)tb1 * Dd))[tid] = acc1;
}

// ===========================================================================
extern "C" void kernel_launch(void* const* d_in, const int* in_sizes, int n_in,
                              void* d_out, int out_size) {
    const float* inputs  = (const float*)d_in[0];
    const float* context = (const float*)d_in[1];
    const float* W_in    = (const float*)d_in[2];
    const float* b_in    = (const float*)d_in[3];
    const float* W_ctx   = (const float*)d_in[4];
    const float* b_ctx   = (const float*)d_in[5];
    const float* w_one   = (const float*)d_in[6];
    // d_in[7] = b_one: softmax is shift-invariant -> no effect on outputs.
    float* out = (float*)d_out;

    gemm_kernel<<<320, 256>>>(inputs, context, W_in, b_in, W_ctx, b_ctx);
    attn_kernel<<<Bb * (Tt / TG), 256>>>(context, w_one, out);
}

// round 14
// speedup vs baseline: 1.6937x; 1.0317x over previous
#include <cuda_runtime.h>
#include <cuda_fp16.h>
#include <cstdint>

// Shapes (fixed by the problem)
#define Dd 1024
#define Tt 32
#define Bb 16
#define Ss 128
#define TG 2            // t-values per attn CTA (grid = 256)

// Scratch for the two projection GEMMs — fp16, PRE-SCALED BY 0.5:
//   g_pi = 0.5*(inputs@W_in^T + b_in),  g_pc = 0.5*(context@W_ctx^T + b_ctx)
// They feed ONLY the swish (h = c/2 is exactly what swish needs).
__device__ __half g_pi[Tt * Bb * Dd];
__device__ __half g_pc[Bb * Ss * Dd];

// ===========================================================================
// Helpers
// ===========================================================================
__device__ __forceinline__ uint32_t smem_to_u32(const void* p) {
    uint32_t a;
    asm("{ .reg .u64 t; cvta.to.shared.u64 t, %1; cvt.u32.u64 %0, t; }" : "=r"(a) : "l"(p));
    return a;
}
__device__ __forceinline__ void ldsm_x4(uint32_t* r, uint32_t addr) {
    asm volatile("ldmatrix.sync.aligned.m8n8.x4.shared.b16 {%0,%1,%2,%3}, [%4];"
                 : "=r"(r[0]), "=r"(r[1]), "=r"(r[2]), "=r"(r[3]) : "r"(addr));
}
__device__ __forceinline__ void mma_f16(float* c, const uint32_t* a,
                                        uint32_t b0, uint32_t b1) {
    asm volatile(
        "mma.sync.aligned.m16n8k16.row.col.f32.f16.f16.f32 "
        "{%0,%1,%2,%3}, {%4,%5,%6,%7}, {%8,%9}, {%0,%1,%2,%3};"
        : "+f"(c[0]), "+f"(c[1]), "+f"(c[2]), "+f"(c[3])
        : "r"(a[0]), "r"(a[1]), "r"(a[2]), "r"(a[3]), "r"(b0), "r"(b1));
}
__device__ __forceinline__ uint32_t h2bits(__half2 h) {
    uint32_t r; __builtin_memcpy(&r, &h, 4); return r;
}
__device__ __forceinline__ __half2 bits2h(uint32_t u) {
    __half2 h; __builtin_memcpy(&h, &u, 4); return h;
}
__device__ __forceinline__ void store_hi16(float4 v, char* hp) {
    __half hx = __float2half_rn(v.x), hy = __float2half_rn(v.y);
    __half hz = __float2half_rn(v.z), hw = __float2half_rn(v.w);
    *(uint2*)hp = make_uint2(h2bits(__halves2half2(hx, hy)),
                             h2bits(__halves2half2(hz, hw)));
}
__device__ __forceinline__ uint32_t swz(uint32_t off) {      // SW128 swizzle
    return off ^ ((off >> 3) & 0x70);
}

// ===========================================================================
// fp16 single-MMA GEMM, double-buffered. BM=128, BN=64, KC=32; 256 threads.
// Epilogue: fragments -> smem fp16 tile (pitch 144B, bank-conflict-free)
// -> coalesced uint4 global stores.  (Mainloop identical to R11.)
// Grid: blocks [0,64) -> pi (M=512), [64,320) -> pc (M=2048).
// ===========================================================================
#define BMt 128
#define BNt 64
#define KC  32
#define NCHUNK (Dd / KC)        // 32
#define CPITCH 72               // epilogue smem pitch in halves (144 B)

__global__ void __launch_bounds__(256, 2) gemm_kernel(
    const float* __restrict__ inputs, const float* __restrict__ context,
    const float* __restrict__ W_in,  const float* __restrict__ b_in,
    const float* __restrict__ W_ctx, const float* __restrict__ b_ctx)
{
    __shared__ __align__(1024) char sbuf[2][24576];   // [stage]: A 16384 | B 8192

    const int tid  = threadIdx.x;
    const int wid  = tid >> 5;
    const int lane = tid & 31;

    const float* A; const float* W; const float* bias; __half* Cout; int tile;
    if (blockIdx.x < 64) { A = inputs;  W = W_in;  bias = b_in;  Cout = g_pi; tile = blockIdx.x; }
    else                 { A = context; W = W_ctx; bias = b_ctx; Cout = g_pc; tile = blockIdx.x - 64; }
    const int bm = (tile >> 4) * BMt;
    const int bn = (tile & 15) * BNt;

    const int warp_m = wid & 3;
    const int warp_n = wid >> 2;

    const float* aP[4]; uint32_t aHi[4];
    #pragma unroll
    for (int i = 0; i < 4; i++) {
        const int e = i * 256 + tid;
        aP[i]  = A + (size_t)(bm + (e >> 3)) * Dd + (e & 7) * 4;
        aHi[i] = (uint32_t)((e >> 3) * 128 + (e & 7) * 8);
    }
    const float* bP[2]; uint32_t bHi[2];
    #pragma unroll
    for (int i = 0; i < 2; i++) {
        const int e = i * 256 + tid;
        bP[i]  = W + (size_t)(bn + (e >> 3)) * Dd + (e & 7) * 4;
        bHi[i] = (uint32_t)((e >> 3) * 128 + (e & 7) * 8);
    }

    const int lr  = lane & 7;
    const int grp = lane >> 3;
    const uint32_t rowA0 = (uint32_t)(warp_m * 32 + (grp & 1) * 8 + lr) * 128;
    const uint32_t colA  = (uint32_t)((grp >> 1) * 16);
    const uint32_t rowB0 = (uint32_t)(warp_n * 32 + (grp >> 1) * 8 + lr) * 128;
    const uint32_t colB  = (uint32_t)((grp & 1) * 16);

    float acc[2][4][4];
    #pragma unroll
    for (int mi = 0; mi < 2; mi++)
        #pragma unroll
        for (int ni = 0; ni < 4; ni++)
            #pragma unroll
            for (int j = 0; j < 4; j++) acc[mi][ni][j] = 0.f;

    // prologue: chunk 0 -> stage 0
    float4 ra[4], rb[2];
    #pragma unroll
    for (int i = 0; i < 4; i++) ra[i] = *(const float4*)aP[i];
    #pragma unroll
    for (int i = 0; i < 2; i++) rb[i] = *(const float4*)bP[i];
    #pragma unroll
    for (int i = 0; i < 4; i++)
        store_hi16(ra[i], sbuf[0] + swz(aHi[i]));
    #pragma unroll
    for (int i = 0; i < 2; i++)
        store_hi16(rb[i], sbuf[0] + 16384 + swz(bHi[i]));
    __syncthreads();

    for (int c = 0; c < NCHUNK; c++) {
        const int cur = c & 1, nxt = cur ^ 1;

        if (c + 1 < NCHUNK) {
            const int kb = (c + 1) * KC;
            #pragma unroll
            for (int i = 0; i < 4; i++) ra[i] = *(const float4*)(aP[i] + kb);
            #pragma unroll
            for (int i = 0; i < 2; i++) rb[i] = *(const float4*)(bP[i] + kb);
        }

        const uint32_t baseA = smem_to_u32(sbuf[cur]);
        const uint32_t baseB = baseA + 16384;
        #pragma unroll
        for (int ks = 0; ks < 2; ks++) {
            const uint32_t kOff = (uint32_t)(ks * 32);
            uint32_t ah[2][4], bh[2][4];
            #pragma unroll
            for (int mi = 0; mi < 2; mi++) {
                const uint32_t r = rowA0 + (uint32_t)(mi * 16 * 128);
                ldsm_x4(ah[mi], baseA + swz(r + kOff + colA));
            }
            #pragma unroll
            for (int ng = 0; ng < 2; ng++) {
                const uint32_t r = rowB0 + (uint32_t)(ng * 16 * 128);
                ldsm_x4(bh[ng], baseB + swz(r + kOff + colB));
            }
            #pragma unroll
            for (int mi = 0; mi < 2; mi++)
                #pragma unroll
                for (int ni = 0; ni < 4; ni++) {
                    const int ng = ni >> 1, sel = (ni & 1) * 2;
                    mma_f16(acc[mi][ni], ah[mi], bh[ng][sel], bh[ng][sel + 1]);
                }
        }

        if (c + 1 < NCHUNK) {
            #pragma unroll
            for (int i = 0; i < 4; i++)
                store_hi16(ra[i], sbuf[nxt] + swz(aHi[i]));
            #pragma unroll
            for (int i = 0; i < 2; i++)
                store_hi16(rb[i], sbuf[nxt] + 16384 + swz(bHi[i]));
        }
        __syncthreads();
    }

    // ---- epilogue: fragments -> smem fp16 tile -> coalesced stores ----
    __half* ctile = (__half*)sbuf;          // 128 rows x CPITCH halves = 18432 B
    const int tq = lane >> 2;
    const int tr = lane & 3;
    #pragma unroll
    for (int mi = 0; mi < 2; mi++)
        #pragma unroll
        for (int ni = 0; ni < 4; ni++) {
            const int col  = warp_n * 32 + ni * 8 + tr * 2;      // within tile
            const int row0 = warp_m * 32 + mi * 16 + tq;
            const float2 bv = *(const float2*)(bias + bn + col);
            __half2 h0 = __floats2half2_rn((acc[mi][ni][0] + bv.x) * 0.5f,
                                           (acc[mi][ni][1] + bv.y) * 0.5f);
            __half2 h1 = __floats2half2_rn((acc[mi][ni][2] + bv.x) * 0.5f,
                                           (acc[mi][ni][3] + bv.y) * 0.5f);
            *(__half2*)(ctile + (size_t)row0 * CPITCH + col)       = h0;
            *(__half2*)(ctile + (size_t)(row0 + 8) * CPITCH + col) = h1;
        }
    __syncthreads();
    #pragma unroll
    for (int k = 0; k < 4; k++) {
        const int idx = k * 256 + tid;      // 1024 uint4 = 128 rows x 8
        const int row = idx >> 3, c16 = idx & 7;
        const uint4 v = *(const uint4*)(ctile + (size_t)row * CPITCH + c16 * 8);
        *(uint4*)(Cout + (size_t)(bm + row) * Dd + bn + c16 * 8) = v;
    }
}

// ===========================================================================
// Fused scores -> softmax -> weighted context sum.
// BYTE-IDENTICAL to R11 (passed, 38.3us): packed fp16x2 swish, pi + w_one in
// registers (w as fp32), no prefetch.  TG=2, 256 thr, grid 256, 2 CTAs/SM.
// ===========================================================================
__global__ void __launch_bounds__(256, 2) attn_kernel(
    const float* __restrict__ context,
    const float* __restrict__ w_one,
    float* __restrict__ out)
{
    const int b  = blockIdx.x & (Bb - 1);
    const int tg = blockIdx.x >> 4;          // 0..15 ; t = tg*2 + tt

    __shared__ float s_sc[TG][Ss];

    const int tid  = threadIdx.x;
    const int lane = tid & 31;
    const int warp = tid >> 5;               // 0..7

    const int tb0 = (tg * TG + 0) * Bb + b;
    const int tb1 = tb0 + Bb;

    // pi rows (half, = c/2) for both t's: 4 uint4 each (this lane's d-slice)
    // w_one: 8 float4 in registers (no smem in the score loop at all)
    uint4 rp0[4], rp1[4];
    float4 wA[4], wB[4];
    #pragma unroll
    for (int i = 0; i < 4; i++) {
        const int u = i * 32 + lane;         // uint4 index within a 128-uint4 row
        rp0[i] = ((const uint4*)g_pi)[(size_t)tb0 * 128 + u];
        rp1[i] = ((const uint4*)g_pi)[(size_t)tb1 * 128 + u];
        wA[i]  = ((const float4*)w_one)[u * 2];
        wB[i]  = ((const float4*)w_one)[u * 2 + 1];
    }

    // packed swish+weight: h2 = pi+pc (= c/2); sw = h + h*tanh(h);
    // accumulate sw*w into fp32.
    #define SW2F(piu, pcu, wx, wy, ax, ay)                                \
    {                                                                     \
        __half2 h2_ = __hadd2(bits2h(piu), bits2h(pcu));                  \
        uint32_t tu_;                                                     \
        asm("tanh.approx.f16x2 %0, %1;" : "=r"(tu_) : "r"(h2bits(h2_)));  \
        __half2 sw_ = __hfma2(bits2h(tu_), h2_, h2_);                     \
        float2 f_ = __half22float2(sw_);                                  \
        (ax) = fmaf(f_.x, (wx), (ax));                                    \
        (ay) = fmaf(f_.y, (wy), (ay));                                    \
    }

    // ---- scores: warp handles s = warp, warp+8, ... ----
    const uint4* pcb = (const uint4*)g_pc + (size_t)b * Ss * 128;
    for (int s = warp; s < Ss; s += 8) {
        const uint4* row = pcb + (size_t)s * 128;
        uint4 q[4];
        #pragma unroll
        for (int i = 0; i < 4; i++) q[i] = row[i * 32 + lane];

        float a0[4] = {0.f, 0.f, 0.f, 0.f};
        float a1[4] = {0.f, 0.f, 0.f, 0.f};
        #pragma unroll
        for (int i = 0; i < 4; i++) {
            SW2F(rp0[i].x, q[i].x, wA[i].x, wA[i].y, a0[0], a0[1]);
            SW2F(rp0[i].y, q[i].y, wA[i].z, wA[i].w, a0[2], a0[3]);
            SW2F(rp0[i].z, q[i].z, wB[i].x, wB[i].y, a0[0], a0[1]);
            SW2F(rp0[i].w, q[i].w, wB[i].z, wB[i].w, a0[2], a0[3]);
            SW2F(rp1[i].x, q[i].x, wA[i].x, wA[i].y, a1[0], a1[1]);
            SW2F(rp1[i].y, q[i].y, wA[i].z, wA[i].w, a1[2], a1[3]);
            SW2F(rp1[i].z, q[i].z, wB[i].x, wB[i].y, a1[0], a1[1]);
            SW2F(rp1[i].w, q[i].w, wB[i].z, wB[i].w, a1[2], a1[3]);
        }
        float s0 = (a0[0] + a0[1]) + (a0[2] + a0[3]);
        float s1 = (a1[0] + a1[1]) + (a1[2] + a1[3]);
        #pragma unroll
        for (int o = 16; o > 0; o >>= 1) {
            s0 += __shfl_xor_sync(0xffffffffu, s0, o);
            s1 += __shfl_xor_sync(0xffffffffu, s1, o);
        }
        if (lane == 0) { s_sc[0][s] = s0; s_sc[1][s] = s1; }
    }
    __syncthreads();

    // ---- softmax: warp tt (<2) handles row tt ----
    if (warp < TG) {
        const int tt = warp;
        float v0 = s_sc[tt][lane];
        float v1 = s_sc[tt][lane + 32];
        float v2 = s_sc[tt][lane + 64];
        float v3 = s_sc[tt][lane + 96];
        float m = fmaxf(fmaxf(v0, v1), fmaxf(v2, v3));
        #pragma unroll
        for (int o = 16; o > 0; o >>= 1)
            m = fmaxf(m, __shfl_xor_sync(0xffffffffu, m, o));
        float p0 = __expf(v0 - m), p1 = __expf(v1 - m);
        float p2 = __expf(v2 - m), p3 = __expf(v3 - m);
        float sum = p0 + p1 + p2 + p3;
        #pragma unroll
        for (int o = 16; o > 0; o >>= 1)
            sum += __shfl_xor_sync(0xffffffffu, sum, o);
        const float inv = __fdividef(1.f, sum);
        const int tb = (tg * TG + tt) * Bb + b;
        float* attn_out = out + (size_t)Tt * Bb * Dd + (size_t)tb * Ss;
        p0 *= inv; p1 *= inv; p2 *= inv; p3 *= inv;
        s_sc[tt][lane]      = p0;  attn_out[lane]      = p0;
        s_sc[tt][lane + 32] = p1;  attn_out[lane + 32] = p1;
        s_sc[tt][lane + 64] = p2;  attn_out[lane + 64] = p2;
        s_sc[tt][lane + 96] = p3;  attn_out[lane + 96] = p3;
    }
    __syncthreads();

    // ---- attn_context[t,b,:] = sum_s attn[t,s] * context[b,s,:] ----
    const float4* ctx4 = (const float4*)(context + (size_t)b * Ss * Dd);
    float4 acc0 = make_float4(0.f, 0.f, 0.f, 0.f);
    float4 acc1 = make_float4(0.f, 0.f, 0.f, 0.f);

    #pragma unroll 4
    for (int s = 0; s < Ss; s++) {
        const float4 c = ctx4[(size_t)s * (Dd / 4) + tid];
        const float a0 = s_sc[0][s];
        const float a1 = s_sc[1][s];
        acc0.x = fmaf(a0, c.x, acc0.x);  acc0.y = fmaf(a0, c.y, acc0.y);
        acc0.z = fmaf(a0, c.z, acc0.z);  acc0.w = fmaf(a0, c.w, acc0.w);
        acc1.x = fmaf(a1, c.x, acc1.x);  acc1.y = fmaf(a1, c.y, acc1.y);
        acc1.z = fmaf(a1, c.z, acc1.z);  acc1.w = fmaf(a1, c.w, acc1.w);
    }
    ((float4*)(out + (size_t)tb0 * Dd))[tid] = acc0;
    ((float4*)(out + (size_t)tb1 * Dd))[tid] = acc1;
}

// ===========================================================================
extern "C" void kernel_launch(void* const* d_in, const int* in_sizes, int n_in,
                              void* d_out, int out_size) {
    const float* inputs  = (const float*)d_in[0];
    const float* context = (const float*)d_in[1];
    const float* W_in    = (const float*)d_in[2];
    const float* b_in    = (const float*)d_in[3];
    const float* W_ctx   = (const float*)d_in[4];
    const float* b_ctx   = (const float*)d_in[5];
    const float* w_one   = (const float*)d_in[6];
    // d_in[7] = b_one: softmax is shift-invariant -> no effect on outputs.
    float* out = (float*)d_out;

    gemm_kernel<<<320, 256>>>(inputs, context, W_in, b_in, W_ctx, b_ctx);
    attn_kernel<<<Bb * (Tt / TG), 256>>>(context, w_one, out);
}

// round 15
// speedup vs baseline: 1.7452x; 1.0304x over previous
#include <cuda_runtime.h>
#include <cuda_fp16.h>
#include <cstdint>

// Shapes (fixed by the problem)
#define Dd 1024
#define Tt 32
#define Bb 16
#define Ss 128
#define TG 4            // t-values per attn CTA (grid = 128, 512 threads)

// Scratch for the two projection GEMMs — fp16, PRE-SCALED BY 0.5:
//   g_pi = 0.5*(inputs@W_in^T + b_in),  g_pc = 0.5*(context@W_ctx^T + b_ctx)
// They feed ONLY the swish (h = c/2 is exactly what swish needs).
__device__ __half g_pi[Tt * Bb * Dd];
__device__ __half g_pc[Bb * Ss * Dd];

// ===========================================================================
// Helpers
// ===========================================================================
__device__ __forceinline__ uint32_t smem_to_u32(const void* p) {
    uint32_t a;
    asm("{ .reg .u64 t; cvta.to.shared.u64 t, %1; cvt.u32.u64 %0, t; }" : "=r"(a) : "l"(p));
    return a;
}
__device__ __forceinline__ void ldsm_x4(uint32_t* r, uint32_t addr) {
    asm volatile("ldmatrix.sync.aligned.m8n8.x4.shared.b16 {%0,%1,%2,%3}, [%4];"
                 : "=r"(r[0]), "=r"(r[1]), "=r"(r[2]), "=r"(r[3]) : "r"(addr));
}
__device__ __forceinline__ void mma_f16(float* c, const uint32_t* a,
                                        uint32_t b0, uint32_t b1) {
    asm volatile(
        "mma.sync.aligned.m16n8k16.row.col.f32.f16.f16.f32 "
        "{%0,%1,%2,%3}, {%4,%5,%6,%7}, {%8,%9}, {%0,%1,%2,%3};"
        : "+f"(c[0]), "+f"(c[1]), "+f"(c[2]), "+f"(c[3])
        : "r"(a[0]), "r"(a[1]), "r"(a[2]), "r"(a[3]), "r"(b0), "r"(b1));
}
__device__ __forceinline__ uint32_t h2bits(__half2 h) {
    uint32_t r; __builtin_memcpy(&r, &h, 4); return r;
}
__device__ __forceinline__ __half2 bits2h(uint32_t u) {
    __half2 h; __builtin_memcpy(&h, &u, 4); return h;
}
__device__ __forceinline__ void store_hi16(float4 v, char* hp) {
    __half hx = __float2half_rn(v.x), hy = __float2half_rn(v.y);
    __half hz = __float2half_rn(v.z), hw = __float2half_rn(v.w);
    *(uint2*)hp = make_uint2(h2bits(__halves2half2(hx, hy)),
                             h2bits(__halves2half2(hz, hw)));
}
__device__ __forceinline__ uint32_t swz(uint32_t off) {      // SW128 swizzle
    return off ^ ((off >> 3) & 0x70);
}

// ===========================================================================
// fp16 single-MMA GEMM, double-buffered, KC=64 (full 128B SW128 rows —
// no wasted half-row).  BM=128, BN=64; 256 threads = 8 warps (4m x 2n).
// smem: 2 stages x (A 16KB + B 8KB) = 49152 B.  16 chunks, ONE sync each;
// 32 MMAs per warp between syncs.
// Epilogue: fragments -> smem fp16 tile -> coalesced uint4 stores.
// Grid: blocks [0,64) -> pi (M=512), [64,320) -> pc (M=2048).
// ===========================================================================
#define BMt 128
#define BNt 64
#define KC  64
#define NCHUNK (Dd / KC)        // 16
#define CPITCH 72               // epilogue smem pitch in halves (144 B)

__global__ void __launch_bounds__(256, 2) gemm_kernel(
    const float* __restrict__ inputs, const float* __restrict__ context,
    const float* __restrict__ W_in,  const float* __restrict__ b_in,
    const float* __restrict__ W_ctx, const float* __restrict__ b_ctx)
{
    __shared__ __align__(1024) char sbuf[2][24576];   // [stage]: A 16384 | B 8192

    const int tid  = threadIdx.x;
    const int wid  = tid >> 5;
    const int lane = tid & 31;

    const float* A; const float* W; const float* bias; __half* Cout; int tile;
    if (blockIdx.x < 64) { A = inputs;  W = W_in;  bias = b_in;  Cout = g_pi; tile = blockIdx.x; }
    else                 { A = context; W = W_ctx; bias = b_ctx; Cout = g_pc; tile = blockIdx.x - 64; }
    const int bm = (tile >> 4) * BMt;
    const int bn = (tile & 15) * BNt;

    const int warp_m = wid & 3;
    const int warp_n = wid >> 2;

    // per-thread slots: row block r = i*16 + (tid>>4), float4-col c16 = tid&15
    const int r0  = tid >> 4;
    const int c16 = tid & 15;
    const float* aP0 = A + (size_t)(bm + r0) * Dd + c16 * 4;   // + i*16*Dd
    const float* bP0 = W + (size_t)(bn + r0) * Dd + c16 * 4;
    const uint32_t hOff0 = (uint32_t)(r0 * 128 + c16 * 8);     // + i*2048

    const int lr  = lane & 7;
    const int grp = lane >> 3;
    const uint32_t rowA0 = (uint32_t)(warp_m * 32 + (grp & 1) * 8 + lr) * 128;
    const uint32_t colA  = (uint32_t)((grp >> 1) * 16);
    const uint32_t rowB0 = (uint32_t)(warp_n * 32 + (grp >> 1) * 8 + lr) * 128;
    const uint32_t colB  = (uint32_t)((grp & 1) * 16);

    float acc[2][4][4];
    #pragma unroll
    for (int mi = 0; mi < 2; mi++)
        #pragma unroll
        for (int ni = 0; ni < 4; ni++)
            #pragma unroll
            for (int j = 0; j < 4; j++) acc[mi][ni][j] = 0.f;

    // prologue: chunk 0 -> stage 0
    float4 ra[8], rb[4];
    #pragma unroll
    for (int i = 0; i < 8; i++) ra[i] = *(const float4*)(aP0 + (size_t)i * 16 * Dd);
    #pragma unroll
    for (int i = 0; i < 4; i++) rb[i] = *(const float4*)(bP0 + (size_t)i * 16 * Dd);
    #pragma unroll
    for (int i = 0; i < 8; i++)
        store_hi16(ra[i], sbuf[0] + swz(hOff0 + i * 2048));
    #pragma unroll
    for (int i = 0; i < 4; i++)
        store_hi16(rb[i], sbuf[0] + 16384 + swz(hOff0 + i * 2048));
    __syncthreads();

    for (int c = 0; c < NCHUNK; c++) {
        const int cur = c & 1, nxt = cur ^ 1;

        if (c + 1 < NCHUNK) {
            const int kb = (c + 1) * KC;
            #pragma unroll
            for (int i = 0; i < 8; i++) ra[i] = *(const float4*)(aP0 + (size_t)i * 16 * Dd + kb);
            #pragma unroll
            for (int i = 0; i < 4; i++) rb[i] = *(const float4*)(bP0 + (size_t)i * 16 * Dd + kb);
        }

        const uint32_t baseA = smem_to_u32(sbuf[cur]);
        const uint32_t baseB = baseA + 16384;
        #pragma unroll
        for (int ks = 0; ks < 4; ks++) {
            const uint32_t kOff = (uint32_t)(ks * 32);
            uint32_t ah[2][4], bh[2][4];
            #pragma unroll
            for (int mi = 0; mi < 2; mi++) {
                const uint32_t r = rowA0 + (uint32_t)(mi * 16 * 128);
                ldsm_x4(ah[mi], baseA + swz(r + kOff + colA));
            }
            #pragma unroll
            for (int ng = 0; ng < 2; ng++) {
                const uint32_t r = rowB0 + (uint32_t)(ng * 16 * 128);
                ldsm_x4(bh[ng], baseB + swz(r + kOff + colB));
            }
            #pragma unroll
            for (int mi = 0; mi < 2; mi++)
                #pragma unroll
                for (int ni = 0; ni < 4; ni++) {
                    const int ng = ni >> 1, sel = (ni & 1) * 2;
                    mma_f16(acc[mi][ni], ah[mi], bh[ng][sel], bh[ng][sel + 1]);
                }
        }

        if (c + 1 < NCHUNK) {
            #pragma unroll
            for (int i = 0; i < 8; i++)
                store_hi16(ra[i], sbuf[nxt] + swz(hOff0 + i * 2048));
            #pragma unroll
            for (int i = 0; i < 4; i++)
                store_hi16(rb[i], sbuf[nxt] + 16384 + swz(hOff0 + i * 2048));
        }
        __syncthreads();
    }

    // ---- epilogue: fragments -> smem fp16 tile -> coalesced stores ----
    __half* ctile = (__half*)sbuf;          // 128 rows x CPITCH halves = 18432 B
    const int tq = lane >> 2;
    const int tr = lane & 3;
    #pragma unroll
    for (int mi = 0; mi < 2; mi++)
        #pragma unroll
        for (int ni = 0; ni < 4; ni++) {
            const int col  = warp_n * 32 + ni * 8 + tr * 2;      // within tile
            const int row0 = warp_m * 32 + mi * 16 + tq;
            const float2 bv = *(const float2*)(bias + bn + col);
            __half2 h0 = __floats2half2_rn((acc[mi][ni][0] + bv.x) * 0.5f,
                                           (acc[mi][ni][1] + bv.y) * 0.5f);
            __half2 h1 = __floats2half2_rn((acc[mi][ni][2] + bv.x) * 0.5f,
                                           (acc[mi][ni][3] + bv.y) * 0.5f);
            *(__half2*)(ctile + (size_t)row0 * CPITCH + col)       = h0;
            *(__half2*)(ctile + (size_t)(row0 + 8) * CPITCH + col) = h1;
        }
    __syncthreads();
    #pragma unroll
    for (int k = 0; k < 4; k++) {
        const int idx = k * 256 + tid;      // 1024 uint4 = 128 rows x 8
        const int row = idx >> 3, cc = idx & 7;
        const uint4 v = *(const uint4*)(ctile + (size_t)row * CPITCH + cc * 8);
        *(uint4*)(Cout + (size_t)(bm + row) * Dd + bn + cc * 8) = v;
    }
}

// ===========================================================================
// Fused scores -> softmax -> weighted context sum.
// TG=4, 512 threads, grid 128 (16 warps/SM).  Score loop: packed fp16x2
// swish, pi (4 t's) + w_one (fp16x2) in registers; pc streamed.
// Final sum: s-range split across the two 256-thread halves so each
// (s,col) context element is read exactly ONCE per CTA; halves combined
// through a 16 KB smem stage.  Context+pc L2 traffic halved vs TG=2.
// ===========================================================================
__global__ void __launch_bounds__(512, 1) attn_kernel(
    const float* __restrict__ context,
    const float* __restrict__ w_one,
    float* __restrict__ out)
{
    const int b  = blockIdx.x & (Bb - 1);
    const int tg = blockIdx.x >> 4;          // 0..7 ; t = tg*4 + tt

    __shared__ float  s_sc[TG][Ss];
    __shared__ __align__(16) float4 s_part[TG][Dd / 4];   // 16 KB staging

    const int tid  = threadIdx.x;
    const int lane = tid & 31;
    const int warp = tid >> 5;               // 0..15

    int tbs[TG];
    #pragma unroll
    for (int tt = 0; tt < TG; tt++) tbs[tt] = (tg * TG + tt) * Bb + b;

    // pi rows (half = c/2) for all 4 t's + w_one as fp16x2, in registers
    uint4 rp[TG][4];
    uint32_t rw[4][4];
    #pragma unroll
    for (int i = 0; i < 4; i++) {
        const int u = i * 32 + lane;         // uint4 index within 128-uint4 row
        #pragma unroll
        for (int tt = 0; tt < TG; tt++)
            rp[tt][i] = ((const uint4*)g_pi)[(size_t)tbs[tt] * 128 + u];
        const float4 wA = ((const float4*)w_one)[u * 2];
        const float4 wB = ((const float4*)w_one)[u * 2 + 1];
        rw[i][0] = h2bits(__floats2half2_rn(wA.x, wA.y));
        rw[i][1] = h2bits(__floats2half2_rn(wA.z, wA.w));
        rw[i][2] = h2bits(__floats2half2_rn(wB.x, wB.y));
        rw[i][3] = h2bits(__floats2half2_rn(wB.z, wB.w));
    }

    // packed swish+weight: h2 = pi+pc (= c/2); sw = h + h*tanh(h);
    // pr = sw*w (fp16); accumulate into fp32.
    #define SW2(piu, pcu, wu, ax, ay)                                     \
    {                                                                     \
        __half2 h2_ = __hadd2(bits2h(piu), bits2h(pcu));                  \
        uint32_t tu_;                                                     \
        asm("tanh.approx.f16x2 %0, %1;" : "=r"(tu_) : "r"(h2bits(h2_)));  \
        __half2 sw_ = __hfma2(bits2h(tu_), h2_, h2_);                     \
        float2 f_ = __half22float2(__hmul2(sw_, bits2h(wu)));             \
        (ax) += f_.x; (ay) += f_.y;                                       \
    }

    // ---- scores: warp handles s = warp, warp+16, ... (8 iters) ----
    const uint4* pcb = (const uint4*)g_pc + (size_t)b * Ss * 128;
    for (int s = warp; s < Ss; s += 16) {
        const uint4* row = pcb + (size_t)s * 128;
        uint4 q[4];
        #pragma unroll
        for (int i = 0; i < 4; i++) q[i] = row[i * 32 + lane];

        float a[TG][2];
        #pragma unroll
        for (int tt = 0; tt < TG; tt++) { a[tt][0] = 0.f; a[tt][1] = 0.f; }
        #pragma unroll
        for (int i = 0; i < 4; i++) {
            #pragma unroll
            for (int tt = 0; tt < TG; tt++) {
                SW2(rp[tt][i].x, q[i].x, rw[i][0], a[tt][0], a[tt][1]);
                SW2(rp[tt][i].y, q[i].y, rw[i][1], a[tt][0], a[tt][1]);
                SW2(rp[tt][i].z, q[i].z, rw[i][2], a[tt][0], a[tt][1]);
                SW2(rp[tt][i].w, q[i].w, rw[i][3], a[tt][0], a[tt][1]);
            }
        }
        #pragma unroll
        for (int tt = 0; tt < TG; tt++) {
            float v = a[tt][0] + a[tt][1];
            #pragma unroll
            for (int o = 16; o > 0; o >>= 1)
                v += __shfl_xor_sync(0xffffffffu, v, o);
            if (lane == 0) s_sc[tt][s] = v;
        }
    }
    __syncthreads();

    // ---- softmax: warp tt (<4) handles row tt ----
    if (warp < TG) {
        const int tt = warp;
        float v0 = s_sc[tt][lane];
        float v1 = s_sc[tt][lane + 32];
        float v2 = s_sc[tt][lane + 64];
        float v3 = s_sc[tt][lane + 96];
        float m = fmaxf(fmaxf(v0, v1), fmaxf(v2, v3));
        #pragma unroll
        for (int o = 16; o > 0; o >>= 1)
            m = fmaxf(m, __shfl_xor_sync(0xffffffffu, m, o));
        float p0 = __expf(v0 - m), p1 = __expf(v1 - m);
        float p2 = __expf(v2 - m), p3 = __expf(v3 - m);
        float sum = p0 + p1 + p2 + p3;
        #pragma unroll
        for (int o = 16; o > 0; o >>= 1)
            sum += __shfl_xor_sync(0xffffffffu, sum, o);
        const float inv = __fdividef(1.f, sum);
        float* attn_out = out + (size_t)Tt * Bb * Dd + (size_t)tbs[tt] * Ss;
        p0 *= inv; p1 *= inv; p2 *= inv; p3 *= inv;
        s_sc[tt][lane]      = p0;  attn_out[lane]      = p0;
        s_sc[tt][lane + 32] = p1;  attn_out[lane + 32] = p1;
        s_sc[tt][lane + 64] = p2;  attn_out[lane + 64] = p2;
        s_sc[tt][lane + 96] = p3;  attn_out[lane + 96] = p3;
    }
    __syncthreads();

    // ---- attn_context: s-split across the two 256-thread halves ----
    const int col = tid & 255;               // float4 column 0..255
    const int sh  = tid >> 8;                // 0 or 1: s-range half
    const float4* ctx4 = (const float4*)(context + (size_t)b * Ss * Dd);
    float4 acc[TG];
    #pragma unroll
    for (int tt = 0; tt < TG; tt++) acc[tt] = make_float4(0.f, 0.f, 0.f, 0.f);

    const int s0 = sh * (Ss / 2);
    #pragma unroll 4
    for (int si = 0; si < Ss / 2; si++) {
        const int s = s0 + si;
        const float4 c = ctx4[(size_t)s * (Dd / 4) + col];
        #pragma unroll
        for (int tt = 0; tt < TG; tt++) {
            const float av = s_sc[tt][s];
            acc[tt].x = fmaf(av, c.x, acc[tt].x);
            acc[tt].y = fmaf(av, c.y, acc[tt].y);
            acc[tt].z = fmaf(av, c.z, acc[tt].z);
            acc[tt].w = fmaf(av, c.w, acc[tt].w);
        }
    }
    if (sh == 1) {
        #pragma unroll
        for (int tt = 0; tt < TG; tt++) s_part[tt][col] = acc[tt];
    }
    __syncthreads();
    if (sh == 0) {
        #pragma unroll
        for (int tt = 0; tt < TG; tt++) {
            const float4 p = s_part[tt][col];
            float4 o;
            o.x = acc[tt].x + p.x;  o.y = acc[tt].y + p.y;
            o.z = acc[tt].z + p.z;  o.w = acc[tt].w + p.w;
            ((float4*)(out + (size_t)tbs[tt] * Dd))[col] = o;
        }
    }
}

// ===========================================================================
extern "C" void kernel_launch(void* const* d_in, const int* in_sizes, int n_in,
                              void* d_out, int out_size) {
    const float* inputs  = (const float*)d_in[0];
    const float* context = (const float*)d_in[1];
    const float* W_in    = (const float*)d_in[2];
    const float* b_in    = (const float*)d_in[3];
    const float* W_ctx   = (const float*)d_in[4];
    const float* b_ctx   = (const float*)d_in[5];
    const float* w_one   = (const float*)d_in[6];
    // d_in[7] = b_one: softmax is shift-invariant -> no effect on outputs.
    float* out = (float*)d_out;

    gemm_kernel<<<320, 256>>>(inputs, context, W_in, b_in, W_ctx, b_ctx);
    attn_kernel<<<Bb * (Tt / TG), 512>>>(context, w_one, out);
}

// round 16
// speedup vs baseline: 1.8398x; 1.0542x over previous
#include <cuda_runtime.h>
#include <cuda_fp16.h>
#include <cstdint>

// Shapes (fixed by the problem)
#define Dd 1024
#define Tt 32
#define Bb 16
#define Ss 128
#define TG 4            // t-values per attn CTA (grid = 128, 512 threads)

// Scratch for the two projection GEMMs — fp16, PRE-SCALED BY 0.5:
//   g_pi = 0.5*(inputs@W_in^T + b_in),  g_pc = 0.5*(context@W_ctx^T + b_ctx)
// They feed ONLY the swish (h = c/2 is exactly what swish needs).
__device__ __half g_pi[Tt * Bb * Dd];
__device__ __half g_pc[Bb * Ss * Dd];

// ===========================================================================
// Helpers
// ===========================================================================
__device__ __forceinline__ uint32_t smem_to_u32(const void* p) {
    uint32_t a;
    asm("{ .reg .u64 t; cvta.to.shared.u64 t, %1; cvt.u32.u64 %0, t; }" : "=r"(a) : "l"(p));
    return a;
}
__device__ __forceinline__ void ldsm_x4(uint32_t* r, uint32_t addr) {
    asm volatile("ldmatrix.sync.aligned.m8n8.x4.shared.b16 {%0,%1,%2,%3}, [%4];"
                 : "=r"(r[0]), "=r"(r[1]), "=r"(r[2]), "=r"(r[3]) : "r"(addr));
}
__device__ __forceinline__ void mma_f16(float* c, const uint32_t* a,
                                        uint32_t b0, uint32_t b1) {
    asm volatile(
        "mma.sync.aligned.m16n8k16.row.col.f32.f16.f16.f32 "
        "{%0,%1,%2,%3}, {%4,%5,%6,%7}, {%8,%9}, {%0,%1,%2,%3};"
        : "+f"(c[0]), "+f"(c[1]), "+f"(c[2]), "+f"(c[3])
        : "r"(a[0]), "r"(a[1]), "r"(a[2]), "r"(a[3]), "r"(b0), "r"(b1));
}
__device__ __forceinline__ uint32_t h2bits(__half2 h) {
    uint32_t r; __builtin_memcpy(&r, &h, 4); return r;
}
__device__ __forceinline__ __half2 bits2h(uint32_t u) {
    __half2 h; __builtin_memcpy(&h, &u, 4); return h;
}
__device__ __forceinline__ void store_hi16(float4 v, char* hp) {
    __half hx = __float2half_rn(v.x), hy = __float2half_rn(v.y);
    __half hz = __float2half_rn(v.z), hw = __float2half_rn(v.w);
    *(uint2*)hp = make_uint2(h2bits(__halves2half2(hx, hy)),
                             h2bits(__halves2half2(hz, hw)));
}
__device__ __forceinline__ uint32_t swz(uint32_t off) {      // SW128 swizzle
    return off ^ ((off >> 3) & 0x70);
}
// packed swish on 2 elems given h = c/2 inputs: sw = h + h*tanh(h)
__device__ __forceinline__ __half2 swish_h2(uint32_t piu, uint32_t pcu) {
    __half2 h2 = __hadd2(bits2h(piu), bits2h(pcu));
    uint32_t tu;
    asm("tanh.approx.f16x2 %0, %1;" : "=r"(tu) : "r"(h2bits(h2)));
    return __hfma2(bits2h(tu), h2, h2);
}

// ===========================================================================
// fp16 single-MMA GEMM — BYTE-IDENTICAL to R15 (double-buffered, KC=64,
// full 128B SW128 rows; staged fp16 epilogue with coalesced uint4 stores).
// Grid: blocks [0,64) -> pi (M=512), [64,320) -> pc (M=2048).
// ===========================================================================
#define BMt 128
#define BNt 64
#define KC  64
#define NCHUNK (Dd / KC)        // 16
#define CPITCH 72               // epilogue smem pitch in halves (144 B)

__global__ void __launch_bounds__(256, 2) gemm_kernel(
    const float* __restrict__ inputs, const float* __restrict__ context,
    const float* __restrict__ W_in,  const float* __restrict__ b_in,
    const float* __restrict__ W_ctx, const float* __restrict__ b_ctx)
{
    __shared__ __align__(1024) char sbuf[2][24576];   // [stage]: A 16384 | B 8192

    const int tid  = threadIdx.x;
    const int wid  = tid >> 5;
    const int lane = tid & 31;

    const float* A; const float* W; const float* bias; __half* Cout; int tile;
    if (blockIdx.x < 64) { A = inputs;  W = W_in;  bias = b_in;  Cout = g_pi; tile = blockIdx.x; }
    else                 { A = context; W = W_ctx; bias = b_ctx; Cout = g_pc; tile = blockIdx.x - 64; }
    const int bm = (tile >> 4) * BMt;
    const int bn = (tile & 15) * BNt;

    const int warp_m = wid & 3;
    const int warp_n = wid >> 2;

    const int r0  = tid >> 4;
    const int c16 = tid & 15;
    const float* aP0 = A + (size_t)(bm + r0) * Dd + c16 * 4;   // + i*16*Dd
    const float* bP0 = W + (size_t)(bn + r0) * Dd + c16 * 4;
    const uint32_t hOff0 = (uint32_t)(r0 * 128 + c16 * 8);     // + i*2048

    const int lr  = lane & 7;
    const int grp = lane >> 3;
    const uint32_t rowA0 = (uint32_t)(warp_m * 32 + (grp & 1) * 8 + lr) * 128;
    const uint32_t colA  = (uint32_t)((grp >> 1) * 16);
    const uint32_t rowB0 = (uint32_t)(warp_n * 32 + (grp >> 1) * 8 + lr) * 128;
    const uint32_t colB  = (uint32_t)((grp & 1) * 16);

    float acc[2][4][4];
    #pragma unroll
    for (int mi = 0; mi < 2; mi++)
        #pragma unroll
        for (int ni = 0; ni < 4; ni++)
            #pragma unroll
            for (int j = 0; j < 4; j++) acc[mi][ni][j] = 0.f;

    // prologue: chunk 0 -> stage 0
    float4 ra[8], rb[4];
    #pragma unroll
    for (int i = 0; i < 8; i++) ra[i] = *(const float4*)(aP0 + (size_t)i * 16 * Dd);
    #pragma unroll
    for (int i = 0; i < 4; i++) rb[i] = *(const float4*)(bP0 + (size_t)i * 16 * Dd);
    #pragma unroll
    for (int i = 0; i < 8; i++)
        store_hi16(ra[i], sbuf[0] + swz(hOff0 + i * 2048));
    #pragma unroll
    for (int i = 0; i < 4; i++)
        store_hi16(rb[i], sbuf[0] + 16384 + swz(hOff0 + i * 2048));
    __syncthreads();

    for (int c = 0; c < NCHUNK; c++) {
        const int cur = c & 1, nxt = cur ^ 1;

        if (c + 1 < NCHUNK) {
            const int kb = (c + 1) * KC;
            #pragma unroll
            for (int i = 0; i < 8; i++) ra[i] = *(const float4*)(aP0 + (size_t)i * 16 * Dd + kb);
            #pragma unroll
            for (int i = 0; i < 4; i++) rb[i] = *(const float4*)(bP0 + (size_t)i * 16 * Dd + kb);
        }

        const uint32_t baseA = smem_to_u32(sbuf[cur]);
        const uint32_t baseB = baseA + 16384;
        #pragma unroll
        for (int ks = 0; ks < 4; ks++) {
            const uint32_t kOff = (uint32_t)(ks * 32);
            uint32_t ah[2][4], bh[2][4];
            #pragma unroll
            for (int mi = 0; mi < 2; mi++) {
                const uint32_t r = rowA0 + (uint32_t)(mi * 16 * 128);
                ldsm_x4(ah[mi], baseA + swz(r + kOff + colA));
            }
            #pragma unroll
            for (int ng = 0; ng < 2; ng++) {
                const uint32_t r = rowB0 + (uint32_t)(ng * 16 * 128);
                ldsm_x4(bh[ng], baseB + swz(r + kOff + colB));
            }
            #pragma unroll
            for (int mi = 0; mi < 2; mi++)
                #pragma unroll
                for (int ni = 0; ni < 4; ni++) {
                    const int ng = ni >> 1, sel = (ni & 1) * 2;
                    mma_f16(acc[mi][ni], ah[mi], bh[ng][sel], bh[ng][sel + 1]);
                }
        }

        if (c + 1 < NCHUNK) {
            #pragma unroll
            for (int i = 0; i < 8; i++)
                store_hi16(ra[i], sbuf[nxt] + swz(hOff0 + i * 2048));
            #pragma unroll
            for (int i = 0; i < 4; i++)
                store_hi16(rb[i], sbuf[nxt] + 16384 + swz(hOff0 + i * 2048));
        }
        __syncthreads();
    }

    // ---- epilogue: fragments -> smem fp16 tile -> coalesced stores ----
    __half* ctile = (__half*)sbuf;          // 128 rows x CPITCH halves = 18432 B
    const int tq = lane >> 2;
    const int tr = lane & 3;
    #pragma unroll
    for (int mi = 0; mi < 2; mi++)
        #pragma unroll
        for (int ni = 0; ni < 4; ni++) {
            const int col  = warp_n * 32 + ni * 8 + tr * 2;      // within tile
            const int row0 = warp_m * 32 + mi * 16 + tq;
            const float2 bv = *(const float2*)(bias + bn + col);
            __half2 h0 = __floats2half2_rn((acc[mi][ni][0] + bv.x) * 0.5f,
                                           (acc[mi][ni][1] + bv.y) * 0.5f);
            __half2 h1 = __floats2half2_rn((acc[mi][ni][2] + bv.x) * 0.5f,
                                           (acc[mi][ni][3] + bv.y) * 0.5f);
            *(__half2*)(ctile + (size_t)row0 * CPITCH + col)       = h0;
            *(__half2*)(ctile + (size_t)(row0 + 8) * CPITCH + col) = h1;
        }
    __syncthreads();
    #pragma unroll
    for (int k = 0; k < 4; k++) {
        const int idx = k * 256 + tid;      // 1024 uint4 = 128 rows x 8
        const int row = idx >> 3, cc = idx & 7;
        const uint4 v = *(const uint4*)(ctile + (size_t)row * CPITCH + cc * 8);
        *(uint4*)(Cout + (size_t)(bm + row) * Dd + bn + cc * 8) = v;
    }
}

// ===========================================================================
// Fused scores -> softmax -> weighted context sum.
// TG=4, 512 threads, grid 128.  Score loop: packed fp16x2 swish with
// PAIRWISE fp16 accumulation — two products chained in a half2
// (HMUL2 then HFMA2) before ONE convert + fp32 add per pair.  This cuts the
// per-element accumulation tail 4 -> 2.5 instructions (the dominant stream).
// pi (4 t's) + w_one (fp16x2) in registers; pc streamed.
// Final sum: s-range split across the two 256-thread halves (each context
// element read once per CTA), combined through a 16 KB smem stage.
// ===========================================================================
__global__ void __launch_bounds__(512, 1) attn_kernel(
    const float* __restrict__ context,
    const float* __restrict__ w_one,
    float* __restrict__ out)
{
    const int b  = blockIdx.x & (Bb - 1);
    const int tg = blockIdx.x >> 4;          // 0..7 ; t = tg*4 + tt

    __shared__ float  s_sc[TG][Ss];
    __shared__ __align__(16) float4 s_part[TG][Dd / 4];   // 16 KB staging

    const int tid  = threadIdx.x;
    const int lane = tid & 31;
    const int warp = tid >> 5;               // 0..15

    int tbs[TG];
    #pragma unroll
    for (int tt = 0; tt < TG; tt++) tbs[tt] = (tg * TG + tt) * Bb + b;

    // pi rows (half = c/2) for all 4 t's + w_one as fp16x2, in registers
    uint4 rp[TG][4];
    uint32_t rw[4][4];
    #pragma unroll
    for (int i = 0; i < 4; i++) {
        const int u = i * 32 + lane;         // uint4 index within 128-uint4 row
        #pragma unroll
        for (int tt = 0; tt < TG; tt++)
            rp[tt][i] = ((const uint4*)g_pi)[(size_t)tbs[tt] * 128 + u];
        const float4 wA = ((const float4*)w_one)[u * 2];
        const float4 wB = ((const float4*)w_one)[u * 2 + 1];
        rw[i][0] = h2bits(__floats2half2_rn(wA.x, wA.y));
        rw[i][1] = h2bits(__floats2half2_rn(wA.z, wA.w));
        rw[i][2] = h2bits(__floats2half2_rn(wB.x, wB.y));
        rw[i][3] = h2bits(__floats2half2_rn(wB.z, wB.w));
    }

    // ---- scores: warp handles s = warp, warp+16, ... (8 iters) ----
    const uint4* pcb = (const uint4*)g_pc + (size_t)b * Ss * 128;
    for (int s = warp; s < Ss; s += 16) {
        const uint4* row = pcb + (size_t)s * 128;
        uint4 q[4];
        #pragma unroll
        for (int i = 0; i < 4; i++) q[i] = row[i * 32 + lane];

        float a[TG][2];
        #pragma unroll
        for (int tt = 0; tt < TG; tt++) { a[tt][0] = 0.f; a[tt][1] = 0.f; }
        #pragma unroll
        for (int i = 0; i < 4; i++) {
            #pragma unroll
            for (int tt = 0; tt < TG; tt++) {
                // pair 1: elements from .x and .y components
                __half2 p0 = __hmul2(swish_h2(rp[tt][i].x, q[i].x), bits2h(rw[i][0]));
                p0 = __hfma2(swish_h2(rp[tt][i].y, q[i].y), bits2h(rw[i][1]), p0);
                const float2 f0 = __half22float2(p0);
                a[tt][0] += f0.x;  a[tt][1] += f0.y;
                // pair 2: elements from .z and .w components
                __half2 p1 = __hmul2(swish_h2(rp[tt][i].z, q[i].z), bits2h(rw[i][2]));
                p1 = __hfma2(swish_h2(rp[tt][i].w, q[i].w), bits2h(rw[i][3]), p1);
                const float2 f1 = __half22float2(p1);
                a[tt][0] += f1.x;  a[tt][1] += f1.y;
            }
        }
        #pragma unroll
        for (int tt = 0; tt < TG; tt++) {
            float v = a[tt][0] + a[tt][1];
            #pragma unroll
            for (int o = 16; o > 0; o >>= 1)
                v += __shfl_xor_sync(0xffffffffu, v, o);
            if (lane == 0) s_sc[tt][s] = v;
        }
    }
    __syncthreads();

    // ---- softmax: warp tt (<4) handles row tt ----
    if (warp < TG) {
        const int tt = warp;
        float v0 = s_sc[tt][lane];
        float v1 = s_sc[tt][lane + 32];
        float v2 = s_sc[tt][lane + 64];
        float v3 = s_sc[tt][lane + 96];
        float m = fmaxf(fmaxf(v0, v1), fmaxf(v2, v3));
        #pragma unroll
        for (int o = 16; o > 0; o >>= 1)
            m = fmaxf(m, __shfl_xor_sync(0xffffffffu, m, o));
        float p0 = __expf(v0 - m), p1 = __expf(v1 - m);
        float p2 = __expf(v2 - m), p3 = __expf(v3 - m);
        float sum = p0 + p1 + p2 + p3;
        #pragma unroll
        for (int o = 16; o > 0; o >>= 1)
            sum += __shfl_xor_sync(0xffffffffu, sum, o);
        const float inv = __fdividef(1.f, sum);
        float* attn_out = out + (size_t)Tt * Bb * Dd + (size_t)tbs[tt] * Ss;
        p0 *= inv; p1 *= inv; p2 *= inv; p3 *= inv;
        s_sc[tt][lane]      = p0;  attn_out[lane]      = p0;
        s_sc[tt][lane + 32] = p1;  attn_out[lane + 32] = p1;
        s_sc[tt][lane + 64] = p2;  attn_out[lane + 64] = p2;
        s_sc[tt][lane + 96] = p3;  attn_out[lane + 96] = p3;
    }
    __syncthreads();

    // ---- attn_context: s-split across the two 256-thread halves ----
    const int col = tid & 255;               // float4 column 0..255
    const int sh  = tid >> 8;                // 0 or 1: s-range half
    const float4* ctx4 = (const float4*)(context + (size_t)b * Ss * Dd);
    float4 acc[TG];
    #pragma unroll
    for (int tt = 0; tt < TG; tt++) acc[tt] = make_float4(0.f, 0.f, 0.f, 0.f);

    const int s0 = sh * (Ss / 2);
    #pragma unroll 8
    for (int si = 0; si < Ss / 2; si++) {
        const int s = s0 + si;
        const float4 c = ctx4[(size_t)s * (Dd / 4) + col];
        #pragma unroll
        for (int tt = 0; tt < TG; tt++) {
            const float av = s_sc[tt][s];
            acc[tt].x = fmaf(av, c.x, acc[tt].x);
            acc[tt].y = fmaf(av, c.y, acc[tt].y);
            acc[tt].z = fmaf(av, c.z, acc[tt].z);
            acc[tt].w = fmaf(av, c.w, acc[tt].w);
        }
    }
    if (sh == 1) {
        #pragma unroll
        for (int tt = 0; tt < TG; tt++) s_part[tt][col] = acc[tt];
    }
    __syncthreads();
    if (sh == 0) {
        #pragma unroll
        for (int tt = 0; tt < TG; tt++) {
            const float4 p = s_part[tt][col];
            float4 o;
            o.x = acc[tt].x + p.x;  o.y = acc[tt].y + p.y;
            o.z = acc[tt].z + p.z;  o.w = acc[tt].w + p.w;
            ((float4*)(out + (size_t)tbs[tt] * Dd))[col] = o;
        }
    }
}

// ===========================================================================
extern "C" void kernel_launch(void* const* d_in, const int* in_sizes, int n_in,
                              void* d_out, int out_size) {
    const float* inputs  = (const float*)d_in[0];
    const float* context = (const float*)d_in[1];
    const float* W_in    = (const float*)d_in[2];
    const float* b_in    = (const float*)d_in[3];
    const float* W_ctx   = (const float*)d_in[4];
    const float* b_ctx   = (const float*)d_in[5];
    const float* w_one   = (const float*)d_in[6];
    // d_in[7] = b_one: softmax is shift-invariant -> no effect on outputs.
    float* out = (float*)d_out;

    gemm_kernel<<<320, 256>>>(inputs, context, W_in, b_in, W_ctx, b_ctx);
    attn_kernel<<<Bb * (Tt / TG), 512>>>(context, w_one, out);
}

// round 17
// speedup vs baseline: 1.9589x; 1.0647x over previous
#include <cuda_runtime.h>
#include <cuda_fp16.h>
#include <cstdint>

// Shapes (fixed by the problem)
#define Dd 1024
#define Tt 32
#define Bb 16
#define Ss 128
#define TG 4            // t-values per attn CTA (grid = 128, 512 threads)

// Scratch for the two projection GEMMs — fp16, PRE-SCALED BY 0.5:
//   g_pi = 0.5*(inputs@W_in^T + b_in),  g_pc = 0.5*(context@W_ctx^T + b_ctx)
__device__ __half g_pi[Tt * Bb * Dd];
__device__ __half g_pc[Bb * Ss * Dd];

// fp16 copies of the GEMM operands (written once by cvt_kernel)
__device__ __half g_in_h [Tt * Bb * Dd];       // 512 x 1024
__device__ __half g_ctx_h[Bb * Ss * Dd];       // 2048 x 1024
__device__ __half g_Win_h [Dd * Dd];           // 1024 x 1024
__device__ __half g_Wctx_h[Dd * Dd];

// ===========================================================================
// Helpers
// ===========================================================================
__device__ __forceinline__ uint32_t smem_to_u32(const void* p) {
    uint32_t a;
    asm("{ .reg .u64 t; cvta.to.shared.u64 t, %1; cvt.u32.u64 %0, t; }" : "=r"(a) : "l"(p));
    return a;
}
__device__ __forceinline__ void ldsm_x4(uint32_t* r, uint32_t addr) {
    asm volatile("ldmatrix.sync.aligned.m8n8.x4.shared.b16 {%0,%1,%2,%3}, [%4];"
                 : "=r"(r[0]), "=r"(r[1]), "=r"(r[2]), "=r"(r[3]) : "r"(addr));
}
__device__ __forceinline__ void mma_f16(float* c, const uint32_t* a,
                                        uint32_t b0, uint32_t b1) {
    asm volatile(
        "mma.sync.aligned.m16n8k16.row.col.f32.f16.f16.f32 "
        "{%0,%1,%2,%3}, {%4,%5,%6,%7}, {%8,%9}, {%0,%1,%2,%3};"
        : "+f"(c[0]), "+f"(c[1]), "+f"(c[2]), "+f"(c[3])
        : "r"(a[0]), "r"(a[1]), "r"(a[2]), "r"(a[3]), "r"(b0), "r"(b1));
}
__device__ __forceinline__ uint32_t h2bits(__half2 h) {
    uint32_t r; __builtin_memcpy(&r, &h, 4); return r;
}
__device__ __forceinline__ __half2 bits2h(uint32_t u) {
    __half2 h; __builtin_memcpy(&h, &u, 4); return h;
}
__device__ __forceinline__ uint32_t swz(uint32_t off) {      // SW128 swizzle
    return off ^ ((off >> 3) & 0x70);
}
// packed swish on 2 elems given h = c/2 inputs: sw = h + h*tanh(h)
__device__ __forceinline__ __half2 swish_h2(uint32_t piu, uint32_t pcu) {
    __half2 h2 = __hadd2(bits2h(piu), bits2h(pcu));
    uint32_t tu;
    asm("tanh.approx.f16x2 %0, %1;" : "=r"(tu) : "r"(h2bits(h2)));
    return __hfma2(bits2h(tu), h2, h2);
}

// ===========================================================================
// One-shot fp32 -> fp16 conversion of all GEMM operands (each elem ONCE).
// 1,179,648 float4s total; grid-strided not needed (grid sized exactly).
// ===========================================================================
#define CVT_N_IN   (Tt * Bb * Dd / 4)          // 131072
#define CVT_N_CTX  (Bb * Ss * Dd / 4)          // 524288
#define CVT_N_W    (Dd * Dd / 4)               // 262144
#define CVT_TOTAL  (CVT_N_IN + CVT_N_CTX + 2 * CVT_N_W)   // 1179648

__global__ void __launch_bounds__(256) cvt_kernel(
    const float* __restrict__ inputs, const float* __restrict__ context,
    const float* __restrict__ W_in,  const float* __restrict__ W_ctx)
{
    const int i = blockIdx.x * 256 + threadIdx.x;
    const float4* src; __half* dst; int l;
    if (i < CVT_N_IN)                          { src = (const float4*)inputs;  dst = g_in_h;   l = i; }
    else if (i < CVT_N_IN + CVT_N_CTX)         { src = (const float4*)context; dst = g_ctx_h;  l = i - CVT_N_IN; }
    else if (i < CVT_N_IN + CVT_N_CTX + CVT_N_W){ src = (const float4*)W_in;   dst = g_Win_h;  l = i - CVT_N_IN - CVT_N_CTX; }
    else                                       { src = (const float4*)W_ctx;  dst = g_Wctx_h; l = i - CVT_N_IN - CVT_N_CTX - CVT_N_W; }
    const float4 v = src[l];
    *(uint2*)(dst + (size_t)l * 4) =
        make_uint2(h2bits(__floats2half2_rn(v.x, v.y)),
                   h2bits(__floats2half2_rn(v.z, v.w)));
}

// ===========================================================================
// fp16 single-MMA GEMM, double-buffered, KC=64; operands are PRE-CONVERTED
// fp16 (no in-loop conversion, half the load bytes).  BM=128, BN=64;
// 256 threads = 8 warps (4m x 2n).  Staged fp16 epilogue (coalesced stores).
// Grid: blocks [0,64) -> pi (M=512), [64,320) -> pc (M=2048).
// ===========================================================================
#define BMt 128
#define BNt 64
#define KC  64
#define NCHUNK (Dd / KC)        // 16
#define CPITCH 72               // epilogue smem pitch in halves (144 B)

__global__ void __launch_bounds__(256, 2) gemm_kernel(
    const float* __restrict__ b_in, const float* __restrict__ b_ctx)
{
    __shared__ __align__(1024) char sbuf[2][24576];   // [stage]: A 16384 | B 8192

    const int tid  = threadIdx.x;
    const int wid  = tid >> 5;
    const int lane = tid & 31;

    const __half* A; const __half* W; const float* bias; __half* Cout; int tile;
    if (blockIdx.x < 64) { A = g_in_h;  W = g_Win_h;  bias = b_in;  Cout = g_pi; tile = blockIdx.x; }
    else                 { A = g_ctx_h; W = g_Wctx_h; bias = b_ctx; Cout = g_pc; tile = blockIdx.x - 64; }
    const int bm = (tile >> 4) * BMt;
    const int bn = (tile & 15) * BNt;

    const int warp_m = wid & 3;
    const int warp_n = wid >> 2;

    // per-thread slots (uint4 = 8 halves):
    //   A tile: 128 rows x 8 u4/row = 1024 u4 -> 4 per thread (e = i*256+tid)
    //   B tile:  64 rows x 8 u4/row =  512 u4 -> 2 per thread
    const __half* aP[4]; uint32_t aOf[4];
    #pragma unroll
    for (int i = 0; i < 4; i++) {
        const int e = i * 256 + tid;
        aP[i]  = A + (size_t)(bm + (e >> 3)) * Dd + (e & 7) * 8;
        aOf[i] = (uint32_t)((e >> 3) * 128 + (e & 7) * 16);
    }
    const __half* bP[2]; uint32_t bOf[2];
    #pragma unroll
    for (int i = 0; i < 2; i++) {
        const int e = i * 256 + tid;
        bP[i]  = W + (size_t)(bn + (e >> 3)) * Dd + (e & 7) * 8;
        bOf[i] = (uint32_t)((e >> 3) * 128 + (e & 7) * 16);
    }

    const int lr  = lane & 7;
    const int grp = lane >> 3;
    const uint32_t rowA0 = (uint32_t)(warp_m * 32 + (grp & 1) * 8 + lr) * 128;
    const uint32_t colA  = (uint32_t)((grp >> 1) * 16);
    const uint32_t rowB0 = (uint32_t)(warp_n * 32 + (grp >> 1) * 8 + lr) * 128;
    const uint32_t colB  = (uint32_t)((grp & 1) * 16);

    float acc[2][4][4];
    #pragma unroll
    for (int mi = 0; mi < 2; mi++)
        #pragma unroll
        for (int ni = 0; ni < 4; ni++)
            #pragma unroll
            for (int j = 0; j < 4; j++) acc[mi][ni][j] = 0.f;

    // prologue: chunk 0 -> stage 0
    uint4 ra[4], rb[2];
    #pragma unroll
    for (int i = 0; i < 4; i++) ra[i] = *(const uint4*)aP[i];
    #pragma unroll
    for (int i = 0; i < 2; i++) rb[i] = *(const uint4*)bP[i];
    #pragma unroll
    for (int i = 0; i < 4; i++) *(uint4*)(sbuf[0] + swz(aOf[i])) = ra[i];
    #pragma unroll
    for (int i = 0; i < 2; i++) *(uint4*)(sbuf[0] + 16384 + swz(bOf[i])) = rb[i];
    __syncthreads();

    for (int c = 0; c < NCHUNK; c++) {
        const int cur = c & 1, nxt = cur ^ 1;

        if (c + 1 < NCHUNK) {
            const int kb = (c + 1) * KC;
            #pragma unroll
            for (int i = 0; i < 4; i++) ra[i] = *(const uint4*)(aP[i] + kb);
            #pragma unroll
            for (int i = 0; i < 2; i++) rb[i] = *(const uint4*)(bP[i] + kb);
        }

        const uint32_t baseA = smem_to_u32(sbuf[cur]);
        const uint32_t baseB = baseA + 16384;
        #pragma unroll
        for (int ks = 0; ks < 4; ks++) {
            const uint32_t kOff = (uint32_t)(ks * 32);
            uint32_t ah[2][4], bh[2][4];
            #pragma unroll
            for (int mi = 0; mi < 2; mi++) {
                const uint32_t r = rowA0 + (uint32_t)(mi * 16 * 128);
                ldsm_x4(ah[mi], baseA + swz(r + kOff + colA));
            }
            #pragma unroll
            for (int ng = 0; ng < 2; ng++) {
                const uint32_t r = rowB0 + (uint32_t)(ng * 16 * 128);
                ldsm_x4(bh[ng], baseB + swz(r + kOff + colB));
            }
            #pragma unroll
            for (int mi = 0; mi < 2; mi++)
                #pragma unroll
                for (int ni = 0; ni < 4; ni++) {
                    const int ng = ni >> 1, sel = (ni & 1) * 2;
                    mma_f16(acc[mi][ni], ah[mi], bh[ng][sel], bh[ng][sel + 1]);
                }
        }

        if (c + 1 < NCHUNK) {
            #pragma unroll
            for (int i = 0; i < 4; i++) *(uint4*)(sbuf[nxt] + swz(aOf[i])) = ra[i];
            #pragma unroll
            for (int i = 0; i < 2; i++) *(uint4*)(sbuf[nxt] + 16384 + swz(bOf[i])) = rb[i];
        }
        __syncthreads();
    }

    // ---- epilogue: fragments -> smem fp16 tile -> coalesced stores ----
    __half* ctile = (__half*)sbuf;          // 128 rows x CPITCH halves = 18432 B
    const int tq = lane >> 2;
    const int tr = lane & 3;
    #pragma unroll
    for (int mi = 0; mi < 2; mi++)
        #pragma unroll
        for (int ni = 0; ni < 4; ni++) {
            const int col  = warp_n * 32 + ni * 8 + tr * 2;      // within tile
            const int row0 = warp_m * 32 + mi * 16 + tq;
            const float2 bv = *(const float2*)(bias + bn + col);
            __half2 h0 = __floats2half2_rn((acc[mi][ni][0] + bv.x) * 0.5f,
                                           (acc[mi][ni][1] + bv.y) * 0.5f);
            __half2 h1 = __floats2half2_rn((acc[mi][ni][2] + bv.x) * 0.5f,
                                           (acc[mi][ni][3] + bv.y) * 0.5f);
            *(__half2*)(ctile + (size_t)row0 * CPITCH + col)       = h0;
            *(__half2*)(ctile + (size_t)(row0 + 8) * CPITCH + col) = h1;
        }
    __syncthreads();
    #pragma unroll
    for (int k = 0; k < 4; k++) {
        const int idx = k * 256 + tid;      // 1024 uint4 = 128 rows x 8
        const int row = idx >> 3, cc = idx & 7;
        const uint4 v = *(const uint4*)(ctile + (size_t)row * CPITCH + cc * 8);
        *(uint4*)(Cout + (size_t)(bm + row) * Dd + bn + cc * 8) = v;
    }
}

// ===========================================================================
// Fused scores -> softmax -> weighted context sum — BYTE-IDENTICAL to R16.
// ===========================================================================
__global__ void __launch_bounds__(512, 1) attn_kernel(
    const float* __restrict__ context,
    const float* __restrict__ w_one,
    float* __restrict__ out)
{
    const int b  = blockIdx.x & (Bb - 1);
    const int tg = blockIdx.x >> 4;          // 0..7 ; t = tg*4 + tt

    __shared__ float  s_sc[TG][Ss];
    __shared__ __align__(16) float4 s_part[TG][Dd / 4];   // 16 KB staging

    const int tid  = threadIdx.x;
    const int lane = tid & 31;
    const int warp = tid >> 5;               // 0..15

    int tbs[TG];
    #pragma unroll
    for (int tt = 0; tt < TG; tt++) tbs[tt] = (tg * TG + tt) * Bb + b;

    uint4 rp[TG][4];
    uint32_t rw[4][4];
    #pragma unroll
    for (int i = 0; i < 4; i++) {
        const int u = i * 32 + lane;
        #pragma unroll
        for (int tt = 0; tt < TG; tt++)
            rp[tt][i] = ((const uint4*)g_pi)[(size_t)tbs[tt] * 128 + u];
        const float4 wA = ((const float4*)w_one)[u * 2];
        const float4 wB = ((const float4*)w_one)[u * 2 + 1];
        rw[i][0] = h2bits(__floats2half2_rn(wA.x, wA.y));
        rw[i][1] = h2bits(__floats2half2_rn(wA.z, wA.w));
        rw[i][2] = h2bits(__floats2half2_rn(wB.x, wB.y));
        rw[i][3] = h2bits(__floats2half2_rn(wB.z, wB.w));
    }

    // ---- scores: warp handles s = warp, warp+16, ... (8 iters) ----
    const uint4* pcb = (const uint4*)g_pc + (size_t)b * Ss * 128;
    for (int s = warp; s < Ss; s += 16) {
        const uint4* row = pcb + (size_t)s * 128;
        uint4 q[4];
        #pragma unroll
        for (int i = 0; i < 4; i++) q[i] = row[i * 32 + lane];

        float a[TG][2];
        #pragma unroll
        for (int tt = 0; tt < TG; tt++) { a[tt][0] = 0.f; a[tt][1] = 0.f; }
        #pragma unroll
        for (int i = 0; i < 4; i++) {
            #pragma unroll
            for (int tt = 0; tt < TG; tt++) {
                __half2 p0 = __hmul2(swish_h2(rp[tt][i].x, q[i].x), bits2h(rw[i][0]));
                p0 = __hfma2(swish_h2(rp[tt][i].y, q[i].y), bits2h(rw[i][1]), p0);
                const float2 f0 = __half22float2(p0);
                a[tt][0] += f0.x;  a[tt][1] += f0.y;
                __half2 p1 = __hmul2(swish_h2(rp[tt][i].z, q[i].z), bits2h(rw[i][2]));
                p1 = __hfma2(swish_h2(rp[tt][i].w, q[i].w), bits2h(rw[i][3]), p1);
                const float2 f1 = __half22float2(p1);
                a[tt][0] += f1.x;  a[tt][1] += f1.y;
            }
        }
        #pragma unroll
        for (int tt = 0; tt < TG; tt++) {
            float v = a[tt][0] + a[tt][1];
            #pragma unroll
            for (int o = 16; o > 0; o >>= 1)
                v += __shfl_xor_sync(0xffffffffu, v, o);
            if (lane == 0) s_sc[tt][s] = v;
        }
    }
    __syncthreads();

    // ---- softmax: warp tt (<4) handles row tt ----
    if (warp < TG) {
        const int tt = warp;
        float v0 = s_sc[tt][lane];
        float v1 = s_sc[tt][lane + 32];
        float v2 = s_sc[tt][lane + 64];
        float v3 = s_sc[tt][lane + 96];
        float m = fmaxf(fmaxf(v0, v1), fmaxf(v2, v3));
        #pragma unroll
        for (int o = 16; o > 0; o >>= 1)
            m = fmaxf(m, __shfl_xor_sync(0xffffffffu, m, o));
        float p0 = __expf(v0 - m), p1 = __expf(v1 - m);
        float p2 = __expf(v2 - m), p3 = __expf(v3 - m);
        float sum = p0 + p1 + p2 + p3;
        #pragma unroll
        for (int o = 16; o > 0; o >>= 1)
            sum += __shfl_xor_sync(0xffffffffu, sum, o);
        const float inv = __fdividef(1.f, sum);
        float* attn_out = out + (size_t)Tt * Bb * Dd + (size_t)tbs[tt] * Ss;
        p0 *= inv; p1 *= inv; p2 *= inv; p3 *= inv;
        s_sc[tt][lane]      = p0;  attn_out[lane]      = p0;
        s_sc[tt][lane + 32] = p1;  attn_out[lane + 32] = p1;
        s_sc[tt][lane + 64] = p2;  attn_out[lane + 64] = p2;
        s_sc[tt][lane + 96] = p3;  attn_out[lane + 96] = p3;
    }
    __syncthreads();

    // ---- attn_context: s-split across the two 256-thread halves ----
    const int col = tid & 255;
    const int sh  = tid >> 8;
    const float4* ctx4 = (const float4*)(context + (size_t)b * Ss * Dd);
    float4 acc[TG];
    #pragma unroll
    for (int tt = 0; tt < TG; tt++) acc[tt] = make_float4(0.f, 0.f, 0.f, 0.f);

    const int s0 = sh * (Ss / 2);
    #pragma unroll 8
    for (int si = 0; si < Ss / 2; si++) {
        const int s = s0 + si;
        const float4 c = ctx4[(size_t)s * (Dd / 4) + col];
        #pragma unroll
        for (int tt = 0; tt < TG; tt++) {
            const float av = s_sc[tt][s];
            acc[tt].x = fmaf(av, c.x, acc[tt].x);
            acc[tt].y = fmaf(av, c.y, acc[tt].y);
            acc[tt].z = fmaf(av, c.z, acc[tt].z);
            acc[tt].w = fmaf(av, c.w, acc[tt].w);
        }
    }
    if (sh == 1) {
        #pragma unroll
        for (int tt = 0; tt < TG; tt++) s_part[tt][col] = acc[tt];
    }
    __syncthreads();
    if (sh == 0) {
        #pragma unroll
        for (int tt = 0; tt < TG; tt++) {
            const float4 p = s_part[tt][col];
            float4 o;
            o.x = acc[tt].x + p.x;  o.y = acc[tt].y + p.y;
            o.z = acc[tt].z + p.z;  o.w = acc[tt].w + p.w;
            ((float4*)(out + (size_t)tbs[tt] * Dd))[col] = o;
        }
    }
}

// ===========================================================================
extern "C" void kernel_launch(void* const* d_in, const int* in_sizes, int n_in,
                              void* d_out, int out_size) {
    const float* inputs  = (const float*)d_in[0];
    const float* context = (const float*)d_in[1];
    const float* W_in    = (const float*)d_in[2];
    const float* b_in    = (const float*)d_in[3];
    const float* W_ctx   = (const float*)d_in[4];
    const float* b_ctx   = (const float*)d_in[5];
    const float* w_one   = (const float*)d_in[6];
    // d_in[7] = b_one: softmax is shift-invariant -> no effect on outputs.
    float* out = (float*)d_out;

    cvt_kernel<<<CVT_TOTAL / 256, 256>>>(inputs, context, W_in, W_ctx);
    gemm_kernel<<<320, 256>>>(b_in, b_ctx);
    attn_kernel<<<Bb * (Tt / TG), 512>>>(context, w_one, out);
}